// round 3
// baseline (speedup 1.0000x reference)
#include <cuda_runtime.h>
#include <cstdint>

#define N_NODES 100000
#define N_EDGES 1600000
#define N_GRAPHS 64
#define EMBED 64
#define HIDDEN 128

// ---------------- scratch (static device globals; no allocation) ----------------
__device__ float g_h0[N_NODES * EMBED];      // embedded features        25.6 MB
__device__ float g_m[N_NODES * HIDDEN];      // h @ W                    51.2 MB
__device__ float g_agg[N_NODES * HIDDEN];    // aggregated (pre-ReLU)    51.2 MB
__device__ int   g_src[N_EDGES];             //                           6.4 MB
__device__ int   g_dst[N_EDGES];             //                           6.4 MB
__device__ float g_coef[N_EDGES];            // dinv[src]*dinv[dst]       6.4 MB
__device__ int   g_batch32[N_NODES];
__device__ float g_dinv[N_NODES];
__device__ int   g_deg[N_NODES];
__device__ float g_pool[N_GRAPHS * HIDDEN];
__device__ float g_cnt[N_GRAPHS];
__device__ int   g_is64;                     // 1 if index arrays are int64, else int32

// ---------------- dtype detection (int64 vs int32 index arrays) ----------------
__global__ void k_detect(const void* ei) {
    // Interpreting int32 data as u64 pairs gives values >= 2^32 whenever the
    // high half (another random node id in [0,1e5)) is nonzero -> essentially
    // guaranteed within 1000 words. True int64 indices are all < N_NODES.
    const unsigned long long* p = (const unsigned long long*)ei;
    int is64 = 1;
    for (int i = 0; i < 1000; ++i) {
        if (p[i] >= (unsigned long long)N_NODES) { is64 = 0; break; }
    }
    g_is64 = is64;
}

__device__ __forceinline__ long long load_idx(const void* p, int i) {
    if (g_is64) return ((const long long*)p)[i];
    return (long long)((const int*)p)[i];
}

// ---------------- prep ----------------
__global__ void k_zero_deg() {
    int i = blockIdx.x * blockDim.x + threadIdx.x;
    if (i < N_NODES) g_deg[i] = 0;
}

__global__ void k_edge_prep(const void* ei) {
    int e = blockIdx.x * blockDim.x + threadIdx.x;
    if (e < N_EDGES) {
        int s = (int)load_idx(ei, e);
        int d = (int)load_idx(ei, N_EDGES + e);
        g_src[e] = s;
        g_dst[e] = d;
        atomicAdd(&g_deg[d], 1);
    }
}

__global__ void k_batch_prep(const void* batch) {
    int i = blockIdx.x * blockDim.x + threadIdx.x;
    if (i < N_NODES) g_batch32[i] = (int)load_idx(batch, i);
}

__global__ void k_dinv() {
    int i = blockIdx.x * blockDim.x + threadIdx.x;
    if (i < N_NODES) g_dinv[i] = rsqrtf((float)g_deg[i] + 1.0f);
}

__global__ void k_coef() {
    int e = blockIdx.x * blockDim.x + threadIdx.x;
    if (e < N_EDGES) g_coef[e] = g_dinv[g_src[e]] * g_dinv[g_dst[e]];
}

// ---------------- embedding gather: h0[i][:] = emb[x[i]][:] ----------------
__global__ void k_embed(const void* x, const float* __restrict__ emb) {
    int t = blockIdx.x * blockDim.x + threadIdx.x;   // over N_NODES * 16 float4s
    if (t < N_NODES * (EMBED / 4)) {
        int node = t >> 4;            // EMBED/4 = 16 float4 per row
        int q = t & 15;
        long long xi = load_idx(x, node);
        reinterpret_cast<float4*>(g_h0)[t] =
            reinterpret_cast<const float4*>(emb)[xi * (EMBED / 4) + q];
    }
}

// ---------------- GEMM + agg init ----------------
// m = act(in) @ W ; agg = m * dinv^2 + b   (self-loop term + bias, pre-seeded
// before the edge kernel scatters the neighbor messages on top).
// Block: 256 threads = 8x32 (ty,tx); tile = 32 rows x 128 cols; 4x4 per thread.
template <int IN, bool RELU_IN, bool FROM_H0>
__global__ void __launch_bounds__(256) k_gemm(const float* __restrict__ W,
                                              const float* __restrict__ b) {
    const float* in = FROM_H0 ? g_h0 : g_agg;
    __shared__ float s_in[32][IN];
    int tid = threadIdx.x;
    int tx = tid & 31;        // col group: cols tx*4 .. tx*4+3
    int ty = tid >> 5;        // row group: rows ty*4 .. ty*4+3
    int row0 = blockIdx.x * 32;

    // Stage 32 input rows (coalesced; consecutive threads -> consecutive k).
    for (int t = tid; t < 32 * IN; t += 256) {
        int r = t / IN;
        int k = t - r * IN;
        float v = in[(long long)(row0 + r) * IN + k];
        if (RELU_IN) v = fmaxf(v, 0.0f);
        s_in[r][k] = v;
    }
    __syncthreads();

    float acc[4][4] = {};
    const float* wp = W + tx * 4;
    int ty4 = ty * 4;

#pragma unroll 4
    for (int k = 0; k < IN; ++k) {
        float4 w = *reinterpret_cast<const float4*>(wp + k * HIDDEN);
#pragma unroll
        for (int r = 0; r < 4; ++r) {
            float a = s_in[ty4 + r][k];
            acc[r][0] += a * w.x;
            acc[r][1] += a * w.y;
            acc[r][2] += a * w.z;
            acc[r][3] += a * w.w;
        }
    }

    float4 bb = *reinterpret_cast<const float4*>(&b[tx * 4]);
#pragma unroll
    for (int r = 0; r < 4; ++r) {
        int row = row0 + ty4 + r;
        float dv = g_dinv[row];
        float sc = dv * dv;
        float4 mv = make_float4(acc[r][0], acc[r][1], acc[r][2], acc[r][3]);
        *reinterpret_cast<float4*>(&g_m[(long long)row * HIDDEN + tx * 4]) = mv;
        float4 av = make_float4(fmaf(mv.x, sc, bb.x), fmaf(mv.y, sc, bb.y),
                                fmaf(mv.z, sc, bb.z), fmaf(mv.w, sc, bb.w));
        *reinterpret_cast<float4*>(&g_agg[(long long)row * HIDDEN + tx * 4]) = av;
    }
}

// ---------------- edge scatter: agg[dst] += coef[e] * m[src] ----------------
// One warp per edge; lane handles 4 floats; vector reduction (REDG.128).
__global__ void __launch_bounds__(256) k_edge() {
    int g = blockIdx.x * blockDim.x + threadIdx.x;
    int e = g >> 5;
    int lane = g & 31;
    if (e >= N_EDGES) return;
    int s = g_src[e];
    int d = g_dst[e];
    float c = g_coef[e];
    float4 v = *reinterpret_cast<const float4*>(&g_m[(long long)s * HIDDEN + lane * 4]);
    float vx = v.x * c, vy = v.y * c, vz = v.z * c, vw = v.w * c;
    float* p = &g_agg[(long long)d * HIDDEN + lane * 4];
    asm volatile("red.global.add.v4.f32 [%0], {%1, %2, %3, %4};"
                 :: "l"(p), "f"(vx), "f"(vy), "f"(vz), "f"(vw)
                 : "memory");
}

// ---------------- pooling ----------------
__global__ void k_zero_pool() {
    int t = blockIdx.x * blockDim.x + threadIdx.x;
    if (t < N_GRAPHS * HIDDEN) g_pool[t] = 0.0f;
    if (t < N_GRAPHS) g_cnt[t] = 0.0f;
}

// batch is sorted -> per-block register accumulation, flush on graph change.
// 128 threads per block, thread t owns hidden dim t; chunk of 512 nodes/block.
#define POOL_CHUNK 512
__global__ void __launch_bounds__(128) k_pool() {
    int t = threadIdx.x;
    int n0 = blockIdx.x * POOL_CHUNK;
    int n1 = n0 + POOL_CHUNK;
    if (n1 > N_NODES) n1 = N_NODES;
    float acc = 0.0f, cnt = 0.0f;
    int cur = -1;
    for (int n = n0; n < n1; ++n) {
        int gidx = g_batch32[n];
        if (gidx != cur) {
            if (cur >= 0) {
                atomicAdd(&g_pool[cur * HIDDEN + t], acc);
                if (t == 0) atomicAdd(&g_cnt[cur], cnt);
            }
            cur = gidx;
            acc = 0.0f;
            cnt = 0.0f;
        }
        acc += fmaxf(g_agg[(long long)n * HIDDEN + t], 0.0f);
        cnt += 1.0f;
    }
    if (cur >= 0) {
        atomicAdd(&g_pool[cur * HIDDEN + t], acc);
        if (t == 0) atomicAdd(&g_cnt[cur], cnt);
    }
}

// ---------------- final: out = (pool / cnt) @ Wp + bp ----------------
__global__ void k_final(const float* __restrict__ Wp, const float* __restrict__ bp,
                        float* __restrict__ out) {
    int t = blockIdx.x * blockDim.x + threadIdx.x;
    if (t >= N_GRAPHS * HIDDEN) return;
    int g = t >> 7;
    int j = t & 127;
    float inv = 1.0f / fmaxf(g_cnt[g], 1.0f);
    float acc = bp[j];
#pragma unroll 8
    for (int k = 0; k < HIDDEN; ++k)
        acc = fmaf(g_pool[g * HIDDEN + k] * inv, Wp[k * HIDDEN + j], acc);
    out[t] = acc;
}

// ---------------- launch ----------------
extern "C" void kernel_launch(void* const* d_in, const int* in_sizes, int n_in,
                              void* d_out, int out_size) {
    const void* x     = d_in[0];                     // int64 (or int32) [N_NODES]
    const void* ei    = d_in[1];                     // int64 (or int32) [2, N_EDGES]
    const void* batch = d_in[2];                     // int64 (or int32) [N_NODES]
    const float* emb  = (const float*)d_in[3];
    const float* W1   = (const float*)d_in[4];
    const float* b1   = (const float*)d_in[5];
    const float* W2   = (const float*)d_in[6];
    const float* b2   = (const float*)d_in[7];
    const float* W3   = (const float*)d_in[8];
    const float* b3   = (const float*)d_in[9];
    const float* Wp   = (const float*)d_in[10];
    const float* bp   = (const float*)d_in[11];
    float* out = (float*)d_out;

    k_detect<<<1, 1>>>(ei);
    k_zero_deg<<<(N_NODES + 255) / 256, 256>>>();
    k_edge_prep<<<(N_EDGES + 255) / 256, 256>>>(ei);
    k_batch_prep<<<(N_NODES + 255) / 256, 256>>>(batch);
    k_dinv<<<(N_NODES + 255) / 256, 256>>>();
    k_coef<<<(N_EDGES + 255) / 256, 256>>>();
    k_embed<<<(N_NODES * (EMBED / 4) + 255) / 256, 256>>>(x, emb);

    // Layer 1 (input: h0, 64-wide, no relu on input)
    k_gemm<EMBED, false, true><<<N_NODES / 32, 256>>>(W1, b1);
    k_edge<<<N_EDGES / 8, 256>>>();
    // Layer 2 (input: relu(agg))
    k_gemm<HIDDEN, true, false><<<N_NODES / 32, 256>>>(W2, b2);
    k_edge<<<N_EDGES / 8, 256>>>();
    // Layer 3
    k_gemm<HIDDEN, true, false><<<N_NODES / 32, 256>>>(W3, b3);
    k_edge<<<N_EDGES / 8, 256>>>();

    k_zero_pool<<<(N_GRAPHS * HIDDEN + 255) / 256, 256>>>();
    k_pool<<<(N_NODES + POOL_CHUNK - 1) / POOL_CHUNK, 128>>>();
    k_final<<<(N_GRAPHS * HIDDEN + 255) / 256, 256>>>(Wp, bp, out);
}

// round 5
// speedup vs baseline: 1.5222x; 1.5222x over previous
#include <cuda_runtime.h>
#include <cstdint>

#define N_NODES 100000
#define N_EDGES 1600000
#define N_GRAPHS 64
#define EMBED 64
#define HIDDEN 128

// ---------------- scratch (static device globals; no allocation) ----------------
__device__ float g_h0[N_NODES * EMBED];        // embedded features      25.6 MB
__device__ float g_m[N_NODES * HIDDEN];        // h @ W                  51.2 MB
__device__ float g_agg[N_NODES * HIDDEN];      // aggregated (pre-ReLU)  51.2 MB
__device__ int   g_csr_src[N_EDGES];           // CSR src per dst-sorted  6.4 MB
__device__ float g_csr_coef[N_EDGES];          // dinv[src]*dinv[dst]     6.4 MB
__device__ int   g_rowptr[N_NODES + 1];
__device__ int   g_cursor[N_NODES];
__device__ int   g_deg[N_NODES];
__device__ float g_dinv[N_NODES];
__device__ int   g_part[512];                  // scan partials
__device__ float g_pool[N_GRAPHS * HIDDEN];
__device__ float g_cnt[N_GRAPHS];
__device__ int   g_is64;

// ---------------- f32x2 helpers (Blackwell packed fp32 FMA) ----------------
__device__ __forceinline__ unsigned long long pack2(float x, float y) {
    unsigned long long r;
    asm("mov.b64 %0, {%1, %2};" : "=l"(r) : "f"(x), "f"(y));
    return r;
}
__device__ __forceinline__ float2 unpack2(unsigned long long v) {
    float2 r;
    asm("mov.b64 {%0, %1}, %2;" : "=f"(r.x), "=f"(r.y) : "l"(v));
    return r;
}
__device__ __forceinline__ void fma2(unsigned long long& d, unsigned long long a,
                                     unsigned long long b) {
    asm("fma.rn.f32x2 %0, %1, %2, %0;" : "+l"(d) : "l"(a), "l"(b));
}

// ---------------- dtype detection (int64 vs int32 index arrays) ----------------
__global__ void k_detect(const void* ei) {
    // int32 data viewed as u64 pairs yields values >= 2^32 whenever the high
    // word (another node id in [0,1e5)) is nonzero -> certain within 1000
    // words. True int64 indices are all < N_NODES.
    const unsigned long long* p = (const unsigned long long*)ei;
    int is64 = 1;
    for (int i = 0; i < 1000; ++i)
        if (p[i] >= (unsigned long long)N_NODES) { is64 = 0; break; }
    g_is64 = is64;
}

__device__ __forceinline__ long long load_idx(const void* p, int i, int is64) {
    if (is64) return ((const long long*)p)[i];
    return (long long)((const int*)p)[i];
}

// ---------------- prep ----------------
__global__ void k_zero() {
    int i = blockIdx.x * blockDim.x + threadIdx.x;
    if (i < N_NODES) g_deg[i] = 0;
    if (i < N_GRAPHS * HIDDEN) g_pool[i] = 0.0f;
    if (i < N_GRAPHS) g_cnt[i] = 0.0f;
}

__global__ void k_count(const void* ei) {
    int is64 = g_is64;
    int e = blockIdx.x * blockDim.x + threadIdx.x;
    if (e < N_EDGES) {
        int d = (int)load_idx(ei, N_EDGES + e, is64);
        atomicAdd(&g_deg[d], 1);
    }
}

// Block-local inclusive scan of degrees (256/block) + dinv computation.
__global__ void __launch_bounds__(256) k_scan1() {
    __shared__ int s[256];
    int tid = threadIdx.x;
    int n = blockIdx.x * 256 + tid;
    int d = (n < N_NODES) ? g_deg[n] : 0;
    if (n < N_NODES) g_dinv[n] = rsqrtf((float)d + 1.0f);
    s[tid] = d;
    __syncthreads();
#pragma unroll
    for (int off = 1; off < 256; off <<= 1) {
        int v = (tid >= off) ? s[tid - off] : 0;
        __syncthreads();
        s[tid] += v;
        __syncthreads();
    }
    if (n < N_NODES) g_rowptr[n] = s[tid] - d;   // block-local exclusive
    if (tid == 255) g_part[blockIdx.x] = s[255];
}

// Scan the 391 block partials (single block).
__global__ void __launch_bounds__(512) k_scan2() {
    __shared__ int s[512];
    int tid = threadIdx.x;
    int v0 = (tid < 391) ? g_part[tid] : 0;
    s[tid] = v0;
    __syncthreads();
#pragma unroll
    for (int off = 1; off < 512; off <<= 1) {
        int v = (tid >= off) ? s[tid - off] : 0;
        __syncthreads();
        s[tid] += v;
        __syncthreads();
    }
    if (tid < 391) g_part[tid] = s[tid] - v0;    // exclusive
}

__global__ void k_scan3() {
    int n = blockIdx.x * blockDim.x + threadIdx.x;
    if (n < N_NODES) {
        int v = g_rowptr[n] + g_part[n >> 8];
        g_rowptr[n] = v;
        g_cursor[n] = v;
    }
    if (n == 0) g_rowptr[N_NODES] = N_EDGES;
}

__global__ void k_csr(const void* ei) {
    int is64 = g_is64;
    int e = blockIdx.x * blockDim.x + threadIdx.x;
    if (e < N_EDGES) {
        int s = (int)load_idx(ei, e, is64);
        int d = (int)load_idx(ei, N_EDGES + e, is64);
        int pos = atomicAdd(&g_cursor[d], 1);
        g_csr_src[pos] = s;
        g_csr_coef[pos] = g_dinv[s] * g_dinv[d];
    }
}

// ---------------- embedding gather ----------------
__global__ void k_embed(const void* x, const float* __restrict__ emb) {
    int is64 = g_is64;
    int t = blockIdx.x * blockDim.x + threadIdx.x;   // N_NODES * 16 float4s
    if (t < N_NODES * (EMBED / 4)) {
        int node = t >> 4;
        int q = t & 15;
        long long xi = load_idx(x, node, is64);
        reinterpret_cast<float4*>(g_h0)[t] =
            reinterpret_cast<const float4*>(emb)[xi * (EMBED / 4) + q];
    }
}

// ---------------- GEMM: m = act(in) @ W  (f32x2 packed FMA) ----------------
// 256 threads = 8x32; tile 32 rows x 128 cols; 4 rows x 4 cols per thread.
template <int IN, bool RELU_IN, bool FROM_H0>
__global__ void __launch_bounds__(256) k_gemm(const float* __restrict__ W) {
    const float* in = FROM_H0 ? g_h0 : g_agg;
    __shared__ float s_in[32][IN];
    int tid = threadIdx.x;
    int tx = tid & 31;
    int ty = tid >> 5;
    int row0 = blockIdx.x * 32;

    for (int t = tid; t < 32 * IN; t += 256) {
        int r = t / IN;
        int k = t - r * IN;
        float v = in[(long long)(row0 + r) * IN + k];
        if (RELU_IN) v = fmaxf(v, 0.0f);
        s_in[r][k] = v;
    }
    __syncthreads();

    unsigned long long acc01[4] = {}, acc23[4] = {};
    const float* wp = W + tx * 4;
    int ty4 = ty * 4;

#pragma unroll 4
    for (int k = 0; k < IN; ++k) {
        float4 w = *reinterpret_cast<const float4*>(wp + k * HIDDEN);
        unsigned long long w01 = pack2(w.x, w.y);
        unsigned long long w23 = pack2(w.z, w.w);
#pragma unroll
        for (int r = 0; r < 4; ++r) {
            float a = s_in[ty4 + r][k];
            unsigned long long aa = pack2(a, a);
            fma2(acc01[r], aa, w01);
            fma2(acc23[r], aa, w23);
        }
    }

#pragma unroll
    for (int r = 0; r < 4; ++r) {
        float2 v01 = unpack2(acc01[r]);
        float2 v23 = unpack2(acc23[r]);
        *reinterpret_cast<float4*>(&g_m[(long long)(row0 + ty4 + r) * HIDDEN + tx * 4]) =
            make_float4(v01.x, v01.y, v23.x, v23.y);
    }
}

// ---------------- edge aggregate (CSR): one warp per dst node ----------------
// agg[n] = sum_{e: dst=n} coef[e]*m[src[e]] + m[n]*dinv[n]^2 + b
__global__ void __launch_bounds__(256) k_edge(const float* __restrict__ b) {
    int w = (blockIdx.x * 256 + threadIdx.x) >> 5;
    int lane = threadIdx.x & 31;
    if (w >= N_NODES) return;
    int r0 = g_rowptr[w];
    int r1 = g_rowptr[w + 1];
    unsigned long long acc0 = 0, acc1 = 0;
#pragma unroll 2
    for (int j = r0; j < r1; ++j) {
        int s = g_csr_src[j];                    // uniform (broadcast) load
        float c = g_csr_coef[j];                 // uniform (broadcast) load
        unsigned long long cc = pack2(c, c);
        ulonglong2 v = *reinterpret_cast<const ulonglong2*>(
            &g_m[(long long)s * HIDDEN + lane * 4]);
        fma2(acc0, cc, v.x);
        fma2(acc1, cc, v.y);
    }
    float dv = g_dinv[w];
    float sc = dv * dv;
    float4 mm = *reinterpret_cast<const float4*>(&g_m[(long long)w * HIDDEN + lane * 4]);
    float4 bb = *reinterpret_cast<const float4*>(&b[lane * 4]);
    float2 a0 = unpack2(acc0);
    float2 a1 = unpack2(acc1);
    float4 out = make_float4(a0.x + fmaf(mm.x, sc, bb.x),
                             a0.y + fmaf(mm.y, sc, bb.y),
                             a1.x + fmaf(mm.z, sc, bb.z),
                             a1.y + fmaf(mm.w, sc, bb.w));
    *reinterpret_cast<float4*>(&g_agg[(long long)w * HIDDEN + lane * 4]) = out;
}

// ---------------- pooling (batch sorted -> register accumulation) ----------------
#define POOL_CHUNK 512
__global__ void __launch_bounds__(128) k_pool(const void* batch) {
    int is64 = g_is64;
    int t = threadIdx.x;
    int n0 = blockIdx.x * POOL_CHUNK;
    int n1 = n0 + POOL_CHUNK;
    if (n1 > N_NODES) n1 = N_NODES;
    float acc = 0.0f, cnt = 0.0f;
    int cur = -1;
    for (int n = n0; n < n1; ++n) {
        int gidx = (int)load_idx(batch, n, is64);   // broadcast load
        if (gidx != cur) {
            if (cur >= 0) {
                atomicAdd(&g_pool[cur * HIDDEN + t], acc);
                if (t == 0) atomicAdd(&g_cnt[cur], cnt);
            }
            cur = gidx;
            acc = 0.0f;
            cnt = 0.0f;
        }
        acc += fmaxf(g_agg[(long long)n * HIDDEN + t], 0.0f);
        cnt += 1.0f;
    }
    if (cur >= 0) {
        atomicAdd(&g_pool[cur * HIDDEN + t], acc);
        if (t == 0) atomicAdd(&g_cnt[cur], cnt);
    }
}

// ---------------- final: out = (pool / cnt) @ Wp + bp ----------------
__global__ void k_final(const float* __restrict__ Wp, const float* __restrict__ bp,
                        float* __restrict__ out) {
    int t = blockIdx.x * blockDim.x + threadIdx.x;
    if (t >= N_GRAPHS * HIDDEN) return;
    int g = t >> 7;
    int j = t & 127;
    float inv = 1.0f / fmaxf(g_cnt[g], 1.0f);
    float acc = bp[j];
#pragma unroll 8
    for (int k = 0; k < HIDDEN; ++k)
        acc = fmaf(g_pool[g * HIDDEN + k] * inv, Wp[k * HIDDEN + j], acc);
    out[t] = acc;
}

// ---------------- launch ----------------
extern "C" void kernel_launch(void* const* d_in, const int* in_sizes, int n_in,
                              void* d_out, int out_size) {
    const void* x     = d_in[0];
    const void* ei    = d_in[1];
    const void* batch = d_in[2];
    const float* emb  = (const float*)d_in[3];
    const float* W1   = (const float*)d_in[4];
    const float* b1   = (const float*)d_in[5];
    const float* W2   = (const float*)d_in[6];
    const float* b2   = (const float*)d_in[7];
    const float* W3   = (const float*)d_in[8];
    const float* b3   = (const float*)d_in[9];
    const float* Wp   = (const float*)d_in[10];
    const float* bp   = (const float*)d_in[11];
    float* out = (float*)d_out;

    k_detect<<<1, 1>>>(ei);
    k_zero<<<(N_NODES + 255) / 256, 256>>>();
    k_count<<<(N_EDGES + 255) / 256, 256>>>(ei);
    k_scan1<<<(N_NODES + 255) / 256, 256>>>();          // 391 blocks
    k_scan2<<<1, 512>>>();
    k_scan3<<<(N_NODES + 255) / 256, 256>>>();
    k_csr<<<(N_EDGES + 255) / 256, 256>>>(ei);
    k_embed<<<(N_NODES * (EMBED / 4) + 255) / 256, 256>>>(x, emb);

    // Layer 1 (input: h0, 64-wide)
    k_gemm<EMBED, false, true><<<N_NODES / 32, 256>>>(W1);
    k_edge<<<(N_NODES * 32 + 255) / 256, 256>>>(b1);
    // Layer 2
    k_gemm<HIDDEN, true, false><<<N_NODES / 32, 256>>>(W2);
    k_edge<<<(N_NODES * 32 + 255) / 256, 256>>>(b2);
    // Layer 3
    k_gemm<HIDDEN, true, false><<<N_NODES / 32, 256>>>(W3);
    k_edge<<<(N_NODES * 32 + 255) / 256, 256>>>(b3);

    k_pool<<<(N_NODES + POOL_CHUNK - 1) / POOL_CHUNK, 128>>>(batch);
    k_final<<<(N_GRAPHS * HIDDEN + 255) / 256, 256>>>(Wp, bp, out);
}

// round 6
// speedup vs baseline: 1.6561x; 1.0880x over previous
#include <cuda_runtime.h>
#include <cuda_fp16.h>
#include <cstdint>

#define N_NODES 100000
#define N_EDGES 1600000
#define N_GRAPHS 64
#define EMBED 64
#define HIDDEN 128

// ---------------- scratch (static device globals; no allocation) ----------------
__device__ float  g_h0[N_NODES * EMBED];        // embedded features     25.6 MB
__device__ __half g_mh[N_NODES * HIDDEN];       // h @ W (fp16)          25.6 MB
__device__ float  g_agg[N_NODES * HIDDEN];      // aggregated (fp32)     51.2 MB
__device__ int2   g_csr[N_EDGES];               // (src, coef-bits)      12.8 MB
__device__ int    g_rowptr[N_NODES + 1];
__device__ int    g_cursor[N_NODES];
__device__ int    g_deg[N_NODES];
__device__ float  g_dinv[N_NODES];
__device__ int    g_part[512];
__device__ float  g_pool[N_GRAPHS * HIDDEN];
__device__ float  g_cnt[N_GRAPHS];
__device__ int    g_is64;

// ---------------- f32x2 helpers (Blackwell packed fp32 FMA) ----------------
__device__ __forceinline__ unsigned long long pack2(float x, float y) {
    unsigned long long r;
    asm("mov.b64 %0, {%1, %2};" : "=l"(r) : "f"(x), "f"(y));
    return r;
}
__device__ __forceinline__ float2 unpack2(unsigned long long v) {
    float2 r;
    asm("mov.b64 {%0, %1}, %2;" : "=f"(r.x), "=f"(r.y) : "l"(v));
    return r;
}
__device__ __forceinline__ void fma2(unsigned long long& d, unsigned long long a,
                                     unsigned long long b) {
    asm("fma.rn.f32x2 %0, %1, %2, %0;" : "+l"(d) : "l"(a), "l"(b));
}

__device__ __forceinline__ long long load_idx(const void* p, int i, int is64) {
    if (is64) return ((const long long*)p)[i];
    return (long long)((const int*)p)[i];
}

// ---------------- init: zero counters + parallel dtype detection ----------------
__global__ void k_init(const void* ei) {
    int i = blockIdx.x * blockDim.x + threadIdx.x;
    if (i < N_NODES) g_deg[i] = 0;
    if (i < N_GRAPHS * HIDDEN) g_pool[i] = 0.0f;
    if (i < N_GRAPHS) g_cnt[i] = 0.0f;
    if (blockIdx.x == 0) {
        // int32 data viewed as u64 pairs exceeds N_NODES whenever the high
        // word is nonzero -> certain within 1000 words. int64 ids stay small.
        __shared__ int s_ok;
        if (threadIdx.x == 0) s_ok = 1;
        __syncthreads();
        const unsigned long long* p = (const unsigned long long*)ei;
        int bad = 0;
        for (int t = threadIdx.x; t < 1000; t += 256)
            if (p[t] >= (unsigned long long)N_NODES) bad = 1;
        if (bad) atomicAnd(&s_ok, 0);
        __syncthreads();
        if (threadIdx.x == 0) g_is64 = s_ok;
    }
}

// ---------------- prep ----------------
__global__ void k_count(const void* ei) {
    int is64 = g_is64;
    int e = blockIdx.x * blockDim.x + threadIdx.x;
    if (e < N_EDGES) {
        int d = (int)load_idx(ei, N_EDGES + e, is64);
        atomicAdd(&g_deg[d], 1);
    }
}

__global__ void __launch_bounds__(256) k_scan1() {
    __shared__ int s[256];
    int tid = threadIdx.x;
    int n = blockIdx.x * 256 + tid;
    int d = (n < N_NODES) ? g_deg[n] : 0;
    if (n < N_NODES) g_dinv[n] = rsqrtf((float)d + 1.0f);
    s[tid] = d;
    __syncthreads();
#pragma unroll
    for (int off = 1; off < 256; off <<= 1) {
        int v = (tid >= off) ? s[tid - off] : 0;
        __syncthreads();
        s[tid] += v;
        __syncthreads();
    }
    if (n < N_NODES) g_rowptr[n] = s[tid] - d;
    if (tid == 255) g_part[blockIdx.x] = s[255];
}

__global__ void __launch_bounds__(512) k_scan2() {
    __shared__ int s[512];
    int tid = threadIdx.x;
    int v0 = (tid < 391) ? g_part[tid] : 0;
    s[tid] = v0;
    __syncthreads();
#pragma unroll
    for (int off = 1; off < 512; off <<= 1) {
        int v = (tid >= off) ? s[tid - off] : 0;
        __syncthreads();
        s[tid] += v;
        __syncthreads();
    }
    if (tid < 391) g_part[tid] = s[tid] - v0;
}

__global__ void k_scan3() {
    int n = blockIdx.x * blockDim.x + threadIdx.x;
    if (n < N_NODES) {
        int v = g_rowptr[n] + g_part[n >> 8];
        g_rowptr[n] = v;
        g_cursor[n] = v;
    }
    if (n == 0) g_rowptr[N_NODES] = N_EDGES;
}

__global__ void k_csr(const void* ei) {
    int is64 = g_is64;
    int e = blockIdx.x * blockDim.x + threadIdx.x;
    if (e < N_EDGES) {
        int s = (int)load_idx(ei, e, is64);
        int d = (int)load_idx(ei, N_EDGES + e, is64);
        int pos = atomicAdd(&g_cursor[d], 1);
        g_csr[pos] = make_int2(s, __float_as_int(g_dinv[s] * g_dinv[d]));
    }
}

// ---------------- embedding gather ----------------
__global__ void k_embed(const void* x, const float* __restrict__ emb) {
    int is64 = g_is64;
    int t = blockIdx.x * blockDim.x + threadIdx.x;   // N_NODES * 16 float4s
    if (t < N_NODES * (EMBED / 4)) {
        int node = t >> 4;
        int q = t & 15;
        long long xi = load_idx(x, node, is64);
        reinterpret_cast<float4*>(g_h0)[t] =
            reinterpret_cast<const float4*>(emb)[xi * (EMBED / 4) + q];
    }
}

// ---------------- GEMM: mh = half(act(in) @ W) ----------------
// 256 threads; tile 64 rows x 128 cols; 8 rows x 4 cols per thread.
// Accumulators packed over row pairs (f32x2).
template <int IN, bool RELU_IN, bool FROM_H0>
__global__ void __launch_bounds__(256) k_gemm(const float* __restrict__ W) {
    const float* in = FROM_H0 ? g_h0 : g_agg;
    __shared__ float s_in[64][IN];
    int tid = threadIdx.x;
    int tx = tid & 31;        // cols tx*4 .. tx*4+3
    int ty = tid >> 5;        // rows ty*8 .. ty*8+7
    int row0 = blockIdx.x * 64;

    for (int t = tid; t < 64 * IN; t += 256) {
        int r = t / IN;
        int k = t - r * IN;
        int row = row0 + r;
        float v = (row < N_NODES) ? in[(size_t)row * IN + k] : 0.0f;
        if (RELU_IN) v = fmaxf(v, 0.0f);
        s_in[r][k] = v;
    }
    __syncthreads();

    unsigned long long acc[4][4] = {};   // [row-pair p][col c]
    const float* wp = W + tx * 4;
    int r0 = ty * 8;

    for (int k = 0; k < IN; k += 4) {
        float4 a[8];
#pragma unroll
        for (int r = 0; r < 8; ++r)
            a[r] = *reinterpret_cast<const float4*>(&s_in[r0 + r][k]);
#pragma unroll
        for (int kk = 0; kk < 4; ++kk) {
            float4 w = *reinterpret_cast<const float4*>(wp + (k + kk) * HIDDEN);
            unsigned long long wd0 = pack2(w.x, w.x);
            unsigned long long wd1 = pack2(w.y, w.y);
            unsigned long long wd2 = pack2(w.z, w.z);
            unsigned long long wd3 = pack2(w.w, w.w);
#pragma unroll
            for (int p = 0; p < 4; ++p) {
                float a0 = reinterpret_cast<const float*>(&a[2 * p])[kk];
                float a1 = reinterpret_cast<const float*>(&a[2 * p + 1])[kk];
                unsigned long long ap = pack2(a0, a1);
                fma2(acc[p][0], ap, wd0);
                fma2(acc[p][1], ap, wd1);
                fma2(acc[p][2], ap, wd2);
                fma2(acc[p][3], ap, wd3);
            }
        }
    }

#pragma unroll
    for (int p = 0; p < 4; ++p) {
        float2 c0 = unpack2(acc[p][0]);
        float2 c1 = unpack2(acc[p][1]);
        float2 c2 = unpack2(acc[p][2]);
        float2 c3 = unpack2(acc[p][3]);
        int row = row0 + r0 + 2 * p;
        if (row < N_NODES) {
            __half2 hv[2] = {__floats2half2_rn(c0.x, c1.x), __floats2half2_rn(c2.x, c3.x)};
            *reinterpret_cast<uint2*>(&g_mh[(size_t)row * HIDDEN + tx * 4]) =
                *reinterpret_cast<uint2*>(hv);
        }
        if (row + 1 < N_NODES) {
            __half2 hv[2] = {__floats2half2_rn(c0.y, c1.y), __floats2half2_rn(c2.y, c3.y)};
            *reinterpret_cast<uint2*>(&g_mh[(size_t)(row + 1) * HIDDEN + tx * 4]) =
                *reinterpret_cast<uint2*>(hv);
        }
    }
}

// ---------------- edge aggregate (CSR): one warp per dst node ----------------
// agg[n] = sum_{e: dst=n} coef[e]*mh[src[e]] + mh[n]*dinv[n]^2 + b   (fp32 acc)
__global__ void __launch_bounds__(256) k_edge(const float* __restrict__ b) {
    int w = (blockIdx.x * 256 + threadIdx.x) >> 5;
    int lane = threadIdx.x & 31;
    if (w >= N_NODES) return;
    int r0 = g_rowptr[w];
    int r1 = g_rowptr[w + 1];
    const uint2* mh = reinterpret_cast<const uint2*>(g_mh);
    unsigned long long acc0 = 0, acc1 = 0;
#pragma unroll 2
    for (int j = r0; j < r1; ++j) {
        int2 e = g_csr[j];                       // uniform (broadcast) 8B load
        float c = __int_as_float(e.y);
        unsigned long long cc = pack2(c, c);
        uint2 raw = mh[(size_t)e.x * (HIDDEN / 4) + lane];   // 8B gather
        float2 f0 = __half22float2(*reinterpret_cast<__half2*>(&raw.x));
        float2 f1 = __half22float2(*reinterpret_cast<__half2*>(&raw.y));
        fma2(acc0, cc, pack2(f0.x, f0.y));
        fma2(acc1, cc, pack2(f1.x, f1.y));
    }
    float dv = g_dinv[w];
    float sc = dv * dv;
    uint2 raw = mh[(size_t)w * (HIDDEN / 4) + lane];
    float2 m0 = __half22float2(*reinterpret_cast<__half2*>(&raw.x));
    float2 m1 = __half22float2(*reinterpret_cast<__half2*>(&raw.y));
    float4 bb = *reinterpret_cast<const float4*>(&b[lane * 4]);
    float2 a0 = unpack2(acc0);
    float2 a1 = unpack2(acc1);
    float4 out = make_float4(a0.x + fmaf(m0.x, sc, bb.x),
                             a0.y + fmaf(m0.y, sc, bb.y),
                             a1.x + fmaf(m1.x, sc, bb.z),
                             a1.y + fmaf(m1.y, sc, bb.w));
    *reinterpret_cast<float4*>(&g_agg[(size_t)w * HIDDEN + lane * 4]) = out;
}

// ---------------- pooling (batch sorted -> register accumulation) ----------------
#define POOL_CHUNK 512
__global__ void __launch_bounds__(128) k_pool(const void* batch) {
    int is64 = g_is64;
    int t = threadIdx.x;
    int n0 = blockIdx.x * POOL_CHUNK;
    int n1 = n0 + POOL_CHUNK;
    if (n1 > N_NODES) n1 = N_NODES;
    float acc = 0.0f, cnt = 0.0f;
    int cur = -1;
    for (int n = n0; n < n1; ++n) {
        int gidx = (int)load_idx(batch, n, is64);   // broadcast load
        if (gidx != cur) {
            if (cur >= 0) {
                atomicAdd(&g_pool[cur * HIDDEN + t], acc);
                if (t == 0) atomicAdd(&g_cnt[cur], cnt);
            }
            cur = gidx;
            acc = 0.0f;
            cnt = 0.0f;
        }
        acc += fmaxf(g_agg[(size_t)n * HIDDEN + t], 0.0f);
        cnt += 1.0f;
    }
    if (cur >= 0) {
        atomicAdd(&g_pool[cur * HIDDEN + t], acc);
        if (t == 0) atomicAdd(&g_cnt[cur], cnt);
    }
}

// ---------------- final: out = (pool / cnt) @ Wp + bp ----------------
__global__ void k_final(const float* __restrict__ Wp, const float* __restrict__ bp,
                        float* __restrict__ out) {
    int t = blockIdx.x * blockDim.x + threadIdx.x;
    if (t >= N_GRAPHS * HIDDEN) return;
    int g = t >> 7;
    int j = t & 127;
    float inv = 1.0f / fmaxf(g_cnt[g], 1.0f);
    float acc = bp[j];
#pragma unroll 8
    for (int k = 0; k < HIDDEN; ++k)
        acc = fmaf(g_pool[g * HIDDEN + k] * inv, Wp[k * HIDDEN + j], acc);
    out[t] = acc;
}

// ---------------- launch ----------------
// Launch order puts gemm layer1 at index 3 (the launch ncu captures).
extern "C" void kernel_launch(void* const* d_in, const int* in_sizes, int n_in,
                              void* d_out, int out_size) {
    const void* x     = d_in[0];
    const void* ei    = d_in[1];
    const void* batch = d_in[2];
    const float* emb  = (const float*)d_in[3];
    const float* W1   = (const float*)d_in[4];
    const float* b1   = (const float*)d_in[5];
    const float* W2   = (const float*)d_in[6];
    const float* b2   = (const float*)d_in[7];
    const float* W3   = (const float*)d_in[8];
    const float* b3   = (const float*)d_in[9];
    const float* Wp   = (const float*)d_in[10];
    const float* bp   = (const float*)d_in[11];
    float* out = (float*)d_out;

    const int GEMM_GRID = (N_NODES + 63) / 64;   // 1563

    k_init<<<(N_NODES + 255) / 256, 256>>>(ei);                          // 0
    k_count<<<(N_EDGES + 255) / 256, 256>>>(ei);                         // 1
    k_embed<<<(N_NODES * (EMBED / 4) + 255) / 256, 256>>>(x, emb);       // 2
    k_gemm<EMBED, false, true><<<GEMM_GRID, 256>>>(W1);                  // 3 <- ncu
    k_scan1<<<(N_NODES + 255) / 256, 256>>>();                           // 4
    k_scan2<<<1, 512>>>();                                               // 5
    k_scan3<<<(N_NODES + 255) / 256, 256>>>();                           // 6
    k_csr<<<(N_EDGES + 255) / 256, 256>>>(ei);                           // 7
    k_edge<<<(N_NODES * 32 + 255) / 256, 256>>>(b1);                     // 8
    k_gemm<HIDDEN, true, false><<<GEMM_GRID, 256>>>(W2);                 // 9
    k_edge<<<(N_NODES * 32 + 255) / 256, 256>>>(b2);                     // 10
    k_gemm<HIDDEN, true, false><<<GEMM_GRID, 256>>>(W3);                 // 11
    k_edge<<<(N_NODES * 32 + 255) / 256, 256>>>(b3);                     // 12
    k_pool<<<(N_NODES + POOL_CHUNK - 1) / POOL_CHUNK, 128>>>(batch);     // 13
    k_final<<<(N_GRAPHS * HIDDEN + 255) / 256, 256>>>(Wp, bp, out);      // 14
}

// round 7
// speedup vs baseline: 2.1729x; 1.3120x over previous
#include <cuda_runtime.h>
#include <cuda_fp16.h>
#include <cstdint>

#define N_NODES 100000
#define N_EDGES 1600000
#define N_GRAPHS 64
#define EMBED 64
#define HIDDEN 128

// ---------------- scratch (static device globals; no allocation) ----------------
__device__ __half g_h0h[N_NODES * EMBED];       // embedded features fp16 12.8 MB
__device__ __half g_mh[N_NODES * HIDDEN];       // h @ W (fp16)           25.6 MB
__device__ float  g_agg[N_NODES * HIDDEN];      // aggregated (fp32)      51.2 MB
__device__ int2   g_csr[N_EDGES];               // (src, coef-bits)       12.8 MB
__device__ int    g_rowptr[N_NODES + 1];
__device__ int    g_cursor[N_NODES];
__device__ int    g_deg[N_NODES];
__device__ float  g_dinv[N_NODES];
__device__ int    g_part[512];
__device__ float  g_pool[N_GRAPHS * HIDDEN];
__device__ float  g_cnt[N_GRAPHS];
__device__ int    g_is64;

// ---------------- f32x2 helpers (edge accumulate) ----------------
__device__ __forceinline__ unsigned long long pack2(float x, float y) {
    unsigned long long r;
    asm("mov.b64 %0, {%1, %2};" : "=l"(r) : "f"(x), "f"(y));
    return r;
}
__device__ __forceinline__ float2 unpack2(unsigned long long v) {
    float2 r;
    asm("mov.b64 {%0, %1}, %2;" : "=f"(r.x), "=f"(r.y) : "l"(v));
    return r;
}
__device__ __forceinline__ void fma2(unsigned long long& d, unsigned long long a,
                                     unsigned long long b) {
    asm("fma.rn.f32x2 %0, %1, %2, %0;" : "+l"(d) : "l"(a), "l"(b));
}

// ---------------- mma / ldmatrix helpers ----------------
__device__ __forceinline__ void ldsm_x4(uint32_t& r0, uint32_t& r1, uint32_t& r2,
                                        uint32_t& r3, uint32_t addr) {
    asm volatile("ldmatrix.sync.aligned.m8n8.x4.shared.b16 {%0,%1,%2,%3}, [%4];"
                 : "=r"(r0), "=r"(r1), "=r"(r2), "=r"(r3) : "r"(addr));
}
__device__ __forceinline__ void ldsm_x4_t(uint32_t& r0, uint32_t& r1, uint32_t& r2,
                                          uint32_t& r3, uint32_t addr) {
    asm volatile("ldmatrix.sync.aligned.m8n8.x4.trans.shared.b16 {%0,%1,%2,%3}, [%4];"
                 : "=r"(r0), "=r"(r1), "=r"(r2), "=r"(r3) : "r"(addr));
}
__device__ __forceinline__ void mma16816(float* c, uint32_t a0, uint32_t a1,
                                         uint32_t a2, uint32_t a3,
                                         uint32_t b0, uint32_t b1) {
    asm volatile(
        "mma.sync.aligned.m16n8k16.row.col.f32.f16.f16.f32 "
        "{%0,%1,%2,%3}, {%4,%5,%6,%7}, {%8,%9}, {%0,%1,%2,%3};"
        : "+f"(c[0]), "+f"(c[1]), "+f"(c[2]), "+f"(c[3])
        : "r"(a0), "r"(a1), "r"(a2), "r"(a3), "r"(b0), "r"(b1));
}

__device__ __forceinline__ long long load_idx(const void* p, int i, int is64) {
    if (is64) return ((const long long*)p)[i];
    return (long long)((const int*)p)[i];
}

// ---------------- init: zero counters + parallel dtype detection ----------------
__global__ void k_init(const void* ei) {
    int i = blockIdx.x * blockDim.x + threadIdx.x;
    if (i < N_NODES) g_deg[i] = 0;
    if (i < N_GRAPHS * HIDDEN) g_pool[i] = 0.0f;
    if (i < N_GRAPHS) g_cnt[i] = 0.0f;
    if (blockIdx.x == 0) {
        __shared__ int s_ok;
        if (threadIdx.x == 0) s_ok = 1;
        __syncthreads();
        const unsigned long long* p = (const unsigned long long*)ei;
        int bad = 0;
        for (int t = threadIdx.x; t < 1000; t += 256)
            if (p[t] >= (unsigned long long)N_NODES) bad = 1;
        if (bad) atomicAnd(&s_ok, 0);
        __syncthreads();
        if (threadIdx.x == 0) g_is64 = s_ok;
    }
}

// ---------------- prep ----------------
__global__ void k_count(const void* ei) {
    int is64 = g_is64;
    int e = blockIdx.x * blockDim.x + threadIdx.x;
    if (e < N_EDGES) {
        int d = (int)load_idx(ei, N_EDGES + e, is64);
        atomicAdd(&g_deg[d], 1);
    }
}

__global__ void __launch_bounds__(256) k_scan1() {
    __shared__ int s[256];
    int tid = threadIdx.x;
    int n = blockIdx.x * 256 + tid;
    int d = (n < N_NODES) ? g_deg[n] : 0;
    if (n < N_NODES) g_dinv[n] = rsqrtf((float)d + 1.0f);
    s[tid] = d;
    __syncthreads();
#pragma unroll
    for (int off = 1; off < 256; off <<= 1) {
        int v = (tid >= off) ? s[tid - off] : 0;
        __syncthreads();
        s[tid] += v;
        __syncthreads();
    }
    if (n < N_NODES) g_rowptr[n] = s[tid] - d;
    if (tid == 255) g_part[blockIdx.x] = s[255];
}

__global__ void __launch_bounds__(512) k_scan2() {
    __shared__ int s[512];
    int tid = threadIdx.x;
    int v0 = (tid < 391) ? g_part[tid] : 0;
    s[tid] = v0;
    __syncthreads();
#pragma unroll
    for (int off = 1; off < 512; off <<= 1) {
        int v = (tid >= off) ? s[tid - off] : 0;
        __syncthreads();
        s[tid] += v;
        __syncthreads();
    }
    if (tid < 391) g_part[tid] = s[tid] - v0;
}

__global__ void k_scan3() {
    int n = blockIdx.x * blockDim.x + threadIdx.x;
    if (n < N_NODES) {
        int v = g_rowptr[n] + g_part[n >> 8];
        g_rowptr[n] = v;
        g_cursor[n] = v;
    }
    if (n == 0) g_rowptr[N_NODES] = N_EDGES;
}

__global__ void k_csr(const void* ei) {
    int is64 = g_is64;
    int e = blockIdx.x * blockDim.x + threadIdx.x;
    if (e < N_EDGES) {
        int s = (int)load_idx(ei, e, is64);
        int d = (int)load_idx(ei, N_EDGES + e, is64);
        int pos = atomicAdd(&g_cursor[d], 1);
        g_csr[pos] = make_int2(s, __float_as_int(g_dinv[s] * g_dinv[d]));
    }
}

// ---------------- embedding gather -> fp16 ----------------
__global__ void k_embed(const void* x, const float* __restrict__ emb) {
    int is64 = g_is64;
    int t = blockIdx.x * blockDim.x + threadIdx.x;   // N_NODES * 16 chunks of 4
    if (t < N_NODES * (EMBED / 4)) {
        int node = t >> 4;
        int q = t & 15;
        long long xi = load_idx(x, node, is64);
        float4 v = reinterpret_cast<const float4*>(emb)[xi * (EMBED / 4) + q];
        __half2 h0 = __floats2half2_rn(v.x, v.y);
        __half2 h1 = __floats2half2_rn(v.z, v.w);
        uint2 u = make_uint2(*reinterpret_cast<uint32_t*>(&h0),
                             *reinterpret_cast<uint32_t*>(&h1));
        reinterpret_cast<uint2*>(g_h0h)[t] = u;
    }
}

// ---------------- tensor-core GEMM: mh = half(act(in) @ W) ----------------
// 256 threads = 8 warps as 4(m) x 2(n); block tile 64 rows x 128 cols.
// A, W staged to smem fp16 with +8-half row pad (conflict-free ldmatrix).
template <int IN, bool RELU_IN, bool FROM_H0>
__global__ void __launch_bounds__(256) k_gemm(const float* __restrict__ W) {
    constexpr int SA = IN + 8;        // halves per A row
    constexpr int SW = HIDDEN + 8;    // halves per W row
    extern __shared__ __half smem[];
    __half* sA = smem;                // 64 x SA
    __half* sW = smem + 64 * SA;      // IN x SW
    int tid = threadIdx.x;
    int row0 = blockIdx.x * 64;

    // ---- stage A (convert to fp16; relu for hidden layers) ----
    if (FROM_H0) {
        for (int t = tid; t < 64 * IN / 4; t += 256) {
            int r = t / (IN / 4);
            int kc = t % (IN / 4);
            int row = row0 + r;
            uint2 v = make_uint2(0u, 0u);
            if (row < N_NODES)
                v = *reinterpret_cast<const uint2*>(&g_h0h[(size_t)row * IN + kc * 4]);
            *reinterpret_cast<uint2*>(&sA[r * SA + kc * 4]) = v;
        }
    } else {
        for (int t = tid; t < 64 * IN / 4; t += 256) {
            int r = t / (IN / 4);
            int kc = t % (IN / 4);
            int row = row0 + r;
            float4 v = make_float4(0.f, 0.f, 0.f, 0.f);
            if (row < N_NODES)
                v = *reinterpret_cast<const float4*>(&g_agg[(size_t)row * IN + kc * 4]);
            if (RELU_IN) {
                v.x = fmaxf(v.x, 0.f); v.y = fmaxf(v.y, 0.f);
                v.z = fmaxf(v.z, 0.f); v.w = fmaxf(v.w, 0.f);
            }
            __half2 h0 = __floats2half2_rn(v.x, v.y);
            __half2 h1 = __floats2half2_rn(v.z, v.w);
            uint2 u = make_uint2(*reinterpret_cast<uint32_t*>(&h0),
                                 *reinterpret_cast<uint32_t*>(&h1));
            *reinterpret_cast<uint2*>(&sA[r * SA + kc * 4]) = u;
        }
    }
    // ---- stage W (IN x HIDDEN fp32 -> fp16) ----
    for (int t = tid; t < IN * HIDDEN / 4; t += 256) {
        int k = t / (HIDDEN / 4);
        int nc = t % (HIDDEN / 4);
        float4 v = *reinterpret_cast<const float4*>(&W[k * HIDDEN + nc * 4]);
        __half2 h0 = __floats2half2_rn(v.x, v.y);
        __half2 h1 = __floats2half2_rn(v.z, v.w);
        uint2 u = make_uint2(*reinterpret_cast<uint32_t*>(&h0),
                             *reinterpret_cast<uint32_t*>(&h1));
        *reinterpret_cast<uint2*>(&sW[k * SW + nc * 4]) = u;
    }
    __syncthreads();

    int lane = tid & 31;
    int wid = tid >> 5;
    int mg = wid >> 1;                // 0..3 : rows mg*16..+15
    int wh = wid & 1;                 // 0..1 : cols wh*64..+63
    int lrow = lane & 15;
    int lcol = lane >> 4;

    float acc[8][4] = {};
    uint32_t aBase = (uint32_t)__cvta_generic_to_shared(sA) +
                     ((mg * 16 + lrow) * SA + lcol * 8) * 2;
    uint32_t wBase = (uint32_t)__cvta_generic_to_shared(sW) +
                     (lrow * SW + wh * 64 + lcol * 8) * 2;

#pragma unroll
    for (int ks = 0; ks < IN / 16; ++ks) {
        uint32_t a0, a1, a2, a3;
        ldsm_x4(a0, a1, a2, a3, aBase + ks * 32);
#pragma unroll
        for (int j = 0; j < 4; ++j) {
            uint32_t b0, b1, b2, b3;
            ldsm_x4_t(b0, b1, b2, b3, wBase + ks * 16 * SW * 2 + j * 32);
            mma16816(acc[2 * j], a0, a1, a2, a3, b0, b1);
            mma16816(acc[2 * j + 1], a0, a1, a2, a3, b2, b3);
        }
    }

    // ---- epilogue: fp16 store ----
    int r_lo = row0 + mg * 16 + (lane >> 2);
    int cbase = wh * 64 + (lane & 3) * 2;
#pragma unroll
    for (int j = 0; j < 8; ++j) {
        int col = cbase + j * 8;
        if (r_lo < N_NODES) {
            __half2 h = __floats2half2_rn(acc[j][0], acc[j][1]);
            *reinterpret_cast<__half2*>(&g_mh[(size_t)r_lo * HIDDEN + col]) = h;
        }
        if (r_lo + 8 < N_NODES) {
            __half2 h = __floats2half2_rn(acc[j][2], acc[j][3]);
            *reinterpret_cast<__half2*>(&g_mh[(size_t)(r_lo + 8) * HIDDEN + col]) = h;
        }
    }
}

// ---------------- edge aggregate (CSR): one warp per dst node ----------------
__global__ void __launch_bounds__(256) k_edge(const float* __restrict__ b) {
    int w = (blockIdx.x * 256 + threadIdx.x) >> 5;
    int lane = threadIdx.x & 31;
    if (w >= N_NODES) return;
    int r0 = g_rowptr[w];
    int r1 = g_rowptr[w + 1];
    const uint2* mh = reinterpret_cast<const uint2*>(g_mh);
    unsigned long long acc0 = 0, acc1 = 0;
#pragma unroll 2
    for (int j = r0; j < r1; ++j) {
        int2 e = g_csr[j];                       // uniform (broadcast) 8B load
        float c = __int_as_float(e.y);
        unsigned long long cc = pack2(c, c);
        uint2 raw = mh[(size_t)e.x * (HIDDEN / 4) + lane];   // 8B gather
        float2 f0 = __half22float2(*reinterpret_cast<__half2*>(&raw.x));
        float2 f1 = __half22float2(*reinterpret_cast<__half2*>(&raw.y));
        fma2(acc0, cc, pack2(f0.x, f0.y));
        fma2(acc1, cc, pack2(f1.x, f1.y));
    }
    float dv = g_dinv[w];
    float sc = dv * dv;
    uint2 raw = mh[(size_t)w * (HIDDEN / 4) + lane];
    float2 m0 = __half22float2(*reinterpret_cast<__half2*>(&raw.x));
    float2 m1 = __half22float2(*reinterpret_cast<__half2*>(&raw.y));
    float4 bb = *reinterpret_cast<const float4*>(&b[lane * 4]);
    float2 a0 = unpack2(acc0);
    float2 a1 = unpack2(acc1);
    float4 out = make_float4(a0.x + fmaf(m0.x, sc, bb.x),
                             a0.y + fmaf(m0.y, sc, bb.y),
                             a1.x + fmaf(m1.x, sc, bb.z),
                             a1.y + fmaf(m1.y, sc, bb.w));
    *reinterpret_cast<float4*>(&g_agg[(size_t)w * HIDDEN + lane * 4]) = out;
}

// ---------------- pooling (batch sorted -> register accumulation) ----------------
#define POOL_CHUNK 512
__global__ void __launch_bounds__(128) k_pool(const void* batch) {
    int is64 = g_is64;
    int t = threadIdx.x;
    int n0 = blockIdx.x * POOL_CHUNK;
    int n1 = n0 + POOL_CHUNK;
    if (n1 > N_NODES) n1 = N_NODES;
    float acc = 0.0f, cnt = 0.0f;
    int cur = -1;
    for (int n = n0; n < n1; ++n) {
        int gidx = (int)load_idx(batch, n, is64);
        if (gidx != cur) {
            if (cur >= 0) {
                atomicAdd(&g_pool[cur * HIDDEN + t], acc);
                if (t == 0) atomicAdd(&g_cnt[cur], cnt);
            }
            cur = gidx;
            acc = 0.0f;
            cnt = 0.0f;
        }
        acc += fmaxf(g_agg[(size_t)n * HIDDEN + t], 0.0f);
        cnt += 1.0f;
    }
    if (cur >= 0) {
        atomicAdd(&g_pool[cur * HIDDEN + t], acc);
        if (t == 0) atomicAdd(&g_cnt[cur], cnt);
    }
}

// ---------------- final: out = (pool / cnt) @ Wp + bp ----------------
__global__ void k_final(const float* __restrict__ Wp, const float* __restrict__ bp,
                        float* __restrict__ out) {
    int t = blockIdx.x * blockDim.x + threadIdx.x;
    if (t >= N_GRAPHS * HIDDEN) return;
    int g = t >> 7;
    int j = t & 127;
    float inv = 1.0f / fmaxf(g_cnt[g], 1.0f);
    float acc = bp[j];
#pragma unroll 8
    for (int k = 0; k < HIDDEN; ++k)
        acc = fmaf(g_pool[g * HIDDEN + k] * inv, Wp[k * HIDDEN + j], acc);
    out[t] = acc;
}

// ---------------- launch ----------------
extern "C" void kernel_launch(void* const* d_in, const int* in_sizes, int n_in,
                              void* d_out, int out_size) {
    const void* x     = d_in[0];
    const void* ei    = d_in[1];
    const void* batch = d_in[2];
    const float* emb  = (const float*)d_in[3];
    const float* W1   = (const float*)d_in[4];
    const float* b1   = (const float*)d_in[5];
    const float* W2   = (const float*)d_in[6];
    const float* b2   = (const float*)d_in[7];
    const float* W3   = (const float*)d_in[8];
    const float* b3   = (const float*)d_in[9];
    const float* Wp   = (const float*)d_in[10];
    const float* bp   = (const float*)d_in[11];
    float* out = (float*)d_out;

    constexpr int SMEM1 = (64 * (EMBED + 8) + EMBED * (HIDDEN + 8)) * 2;    // 26.6 KB
    constexpr int SMEM2 = (64 * (HIDDEN + 8) + HIDDEN * (HIDDEN + 8)) * 2;  // 52.2 KB
    cudaFuncSetAttribute(k_gemm<EMBED, false, true>,
                         cudaFuncAttributeMaxDynamicSharedMemorySize, SMEM1);
    cudaFuncSetAttribute(k_gemm<HIDDEN, true, false>,
                         cudaFuncAttributeMaxDynamicSharedMemorySize, SMEM2);

    const int GEMM_GRID = (N_NODES + 63) / 64;   // 1563

    k_init<<<(N_NODES + 255) / 256, 256>>>(ei);                          // 0
    k_count<<<(N_EDGES + 255) / 256, 256>>>(ei);                         // 1
    k_embed<<<(N_NODES * (EMBED / 4) + 255) / 256, 256>>>(x, emb);       // 2
    k_gemm<EMBED, false, true><<<GEMM_GRID, 256, SMEM1>>>(W1);           // 3 <- ncu
    k_scan1<<<(N_NODES + 255) / 256, 256>>>();                           // 4
    k_scan2<<<1, 512>>>();                                               // 5
    k_scan3<<<(N_NODES + 255) / 256, 256>>>();                           // 6
    k_csr<<<(N_EDGES + 255) / 256, 256>>>(ei);                           // 7
    k_edge<<<(N_NODES * 32 + 255) / 256, 256>>>(b1);                     // 8
    k_gemm<HIDDEN, true, false><<<GEMM_GRID, 256, SMEM2>>>(W2);          // 9
    k_edge<<<(N_NODES * 32 + 255) / 256, 256>>>(b2);                     // 10
    k_gemm<HIDDEN, true, false><<<GEMM_GRID, 256, SMEM2>>>(W3);          // 11
    k_edge<<<(N_NODES * 32 + 255) / 256, 256>>>(b3);                     // 12
    k_pool<<<(N_NODES + POOL_CHUNK - 1) / POOL_CHUNK, 128>>>(batch);     // 13
    k_final<<<(N_GRAPHS * HIDDEN + 255) / 256, 256>>>(Wp, bp, out);      // 14
}

// round 10
// speedup vs baseline: 2.5559x; 1.1762x over previous
#include <cuda_runtime.h>
#include <cuda_fp16.h>
#include <cstdint>

#define N_NODES 100000
#define N_EDGES 1600000
#define N_GRAPHS 64
#define EMBED 64
#define HIDDEN 128

// ---------------- scratch (static device globals; no allocation) ----------------
// NOTE: these are referenced ONLY from device code (never passed as kernel
// arguments from host -- host-side names bind to the shadow symbol, which is
// what tripped the R9 memory-guard violation).
__device__ __half g_h0h[N_NODES * EMBED];       // embedded features fp16 12.8 MB
__device__ __half g_mh[N_NODES * HIDDEN];       // h @ W (fp16)           25.6 MB
__device__ __half g_xh[N_NODES * HIDDEN];       // relu'd activations     25.6 MB
__device__ int2   g_csr[N_EDGES];               // (src, coef-bits)       12.8 MB
__device__ int    g_rowptr[N_NODES + 1];
__device__ int    g_cursor[N_NODES];
__device__ int    g_deg[N_NODES];
__device__ float  g_dinv[N_NODES];
__device__ int    g_part[512];
__device__ float  g_pool[N_GRAPHS * HIDDEN];
__device__ float  g_cnt[N_GRAPHS];
__device__ int    g_is64;

// ---------------- f32x2 helpers (edge accumulate) ----------------
__device__ __forceinline__ unsigned long long pack2(float x, float y) {
    unsigned long long r;
    asm("mov.b64 %0, {%1, %2};" : "=l"(r) : "f"(x), "f"(y));
    return r;
}
__device__ __forceinline__ float2 unpack2(unsigned long long v) {
    float2 r;
    asm("mov.b64 {%0, %1}, %2;" : "=f"(r.x), "=f"(r.y) : "l"(v));
    return r;
}
__device__ __forceinline__ void fma2(unsigned long long& d, unsigned long long a,
                                     unsigned long long b) {
    asm("fma.rn.f32x2 %0, %1, %2, %0;" : "+l"(d) : "l"(a), "l"(b));
}

// ---------------- mma / ldmatrix helpers ----------------
__device__ __forceinline__ void ldsm_x4(uint32_t& r0, uint32_t& r1, uint32_t& r2,
                                        uint32_t& r3, uint32_t addr) {
    asm volatile("ldmatrix.sync.aligned.m8n8.x4.shared.b16 {%0,%1,%2,%3}, [%4];"
                 : "=r"(r0), "=r"(r1), "=r"(r2), "=r"(r3) : "r"(addr));
}
__device__ __forceinline__ void ldsm_x4_t(uint32_t& r0, uint32_t& r1, uint32_t& r2,
                                          uint32_t& r3, uint32_t addr) {
    asm volatile("ldmatrix.sync.aligned.m8n8.x4.trans.shared.b16 {%0,%1,%2,%3}, [%4];"
                 : "=r"(r0), "=r"(r1), "=r"(r2), "=r"(r3) : "r"(addr));
}
__device__ __forceinline__ void mma16816(float* c, uint32_t a0, uint32_t a1,
                                         uint32_t a2, uint32_t a3,
                                         uint32_t b0, uint32_t b1) {
    asm volatile(
        "mma.sync.aligned.m16n8k16.row.col.f32.f16.f16.f32 "
        "{%0,%1,%2,%3}, {%4,%5,%6,%7}, {%8,%9}, {%0,%1,%2,%3};"
        : "+f"(c[0]), "+f"(c[1]), "+f"(c[2]), "+f"(c[3])
        : "r"(a0), "r"(a1), "r"(a2), "r"(a3), "r"(b0), "r"(b1));
}

__device__ __forceinline__ long long load_idx(const void* p, int i, int is64) {
    if (is64) return ((const long long*)p)[i];
    return (long long)((const int*)p)[i];
}

// ---------------- init: zero counters + parallel dtype detection ----------------
__global__ void k_init(const void* ei) {
    int i = blockIdx.x * blockDim.x + threadIdx.x;
    if (i < N_NODES) g_deg[i] = 0;
    if (i < N_GRAPHS * HIDDEN) g_pool[i] = 0.0f;
    if (i < N_GRAPHS) g_cnt[i] = 0.0f;
    if (blockIdx.x == 0) {
        __shared__ int s_ok;
        if (threadIdx.x == 0) s_ok = 1;
        __syncthreads();
        const unsigned long long* p = (const unsigned long long*)ei;
        int bad = 0;
        for (int t = threadIdx.x; t < 1000; t += 256)
            if (p[t] >= (unsigned long long)N_NODES) bad = 1;
        if (bad) atomicAnd(&s_ok, 0);
        __syncthreads();
        if (threadIdx.x == 0) g_is64 = s_ok;
    }
}

// ---------------- fused: degree count + embedding gather ----------------
// N_EDGES == N_NODES * (EMBED/4) == 1.6M threads for both jobs.
__global__ void k_count_embed(const void* ei, const void* x,
                              const float* __restrict__ emb) {
    int is64 = g_is64;
    int t = blockIdx.x * blockDim.x + threadIdx.x;
    if (t < N_EDGES) {
        int d = (int)load_idx(ei, N_EDGES + t, is64);
        atomicAdd(&g_deg[d], 1);
    }
    if (t < N_NODES * (EMBED / 4)) {
        int node = t >> 4;
        int q = t & 15;
        long long xi = load_idx(x, node, is64);
        float4 v = reinterpret_cast<const float4*>(emb)[xi * (EMBED / 4) + q];
        __half2 h0 = __floats2half2_rn(v.x, v.y);
        __half2 h1 = __floats2half2_rn(v.z, v.w);
        uint2 u = make_uint2(*reinterpret_cast<uint32_t*>(&h0),
                             *reinterpret_cast<uint32_t*>(&h1));
        reinterpret_cast<uint2*>(g_h0h)[t] = u;
    }
}

// ---------------- prep scans + CSR build ----------------
__global__ void __launch_bounds__(256) k_scan1() {
    __shared__ int s[256];
    int tid = threadIdx.x;
    int n = blockIdx.x * 256 + tid;
    int d = (n < N_NODES) ? g_deg[n] : 0;
    if (n < N_NODES) g_dinv[n] = rsqrtf((float)d + 1.0f);
    s[tid] = d;
    __syncthreads();
#pragma unroll
    for (int off = 1; off < 256; off <<= 1) {
        int v = (tid >= off) ? s[tid - off] : 0;
        __syncthreads();
        s[tid] += v;
        __syncthreads();
    }
    if (n < N_NODES) g_rowptr[n] = s[tid] - d;
    if (tid == 255) g_part[blockIdx.x] = s[255];
}

__global__ void __launch_bounds__(512) k_scan2() {
    __shared__ int s[512];
    int tid = threadIdx.x;
    int v0 = (tid < 391) ? g_part[tid] : 0;
    s[tid] = v0;
    __syncthreads();
#pragma unroll
    for (int off = 1; off < 512; off <<= 1) {
        int v = (tid >= off) ? s[tid - off] : 0;
        __syncthreads();
        s[tid] += v;
        __syncthreads();
    }
    if (tid < 391) g_part[tid] = s[tid] - v0;
}

__global__ void k_scan3() {
    int n = blockIdx.x * blockDim.x + threadIdx.x;
    if (n < N_NODES) {
        int v = g_rowptr[n] + g_part[n >> 8];
        g_rowptr[n] = v;
        g_cursor[n] = v;
    }
    if (n == 0) g_rowptr[N_NODES] = N_EDGES;
}

__global__ void k_csr(const void* ei) {
    int is64 = g_is64;
    int e = blockIdx.x * blockDim.x + threadIdx.x;
    if (e < N_EDGES) {
        int s = (int)load_idx(ei, e, is64);
        int d = (int)load_idx(ei, N_EDGES + e, is64);
        int pos = atomicAdd(&g_cursor[d], 1);
        g_csr[pos] = make_int2(s, __float_as_int(g_dinv[s] * g_dinv[d]));
    }
}

// ---------------- tensor-core GEMM: g_mh = half(in @ W) ----------------
// Input array selected INSIDE the kernel (device-symbol access only).
// 256 threads = 8 warps as 4(m) x 2(n); block tile 64 rows x 128 cols.
template <int IN, bool FROM_H0>
__global__ void __launch_bounds__(256) k_gemm(const float* __restrict__ W) {
    const __half* in = FROM_H0 ? g_h0h : g_xh;
    constexpr int SA = IN + 8;
    constexpr int SW = HIDDEN + 8;
    extern __shared__ __half smem[];
    __half* sA = smem;                // 64 x SA
    __half* sW = smem + 64 * SA;      // IN x SW
    int tid = threadIdx.x;
    int row0 = blockIdx.x * 64;

    // stage A (fp16 straight copy; already relu'd where applicable)
    for (int t = tid; t < 64 * IN / 4; t += 256) {
        int r = t / (IN / 4);
        int kc = t % (IN / 4);
        int row = row0 + r;
        uint2 v = make_uint2(0u, 0u);
        if (row < N_NODES)
            v = *reinterpret_cast<const uint2*>(&in[(size_t)row * IN + kc * 4]);
        *reinterpret_cast<uint2*>(&sA[r * SA + kc * 4]) = v;
    }
    // stage W (fp32 -> fp16)
    for (int t = tid; t < IN * HIDDEN / 4; t += 256) {
        int k = t / (HIDDEN / 4);
        int nc = t % (HIDDEN / 4);
        float4 v = *reinterpret_cast<const float4*>(&W[k * HIDDEN + nc * 4]);
        __half2 h0 = __floats2half2_rn(v.x, v.y);
        __half2 h1 = __floats2half2_rn(v.z, v.w);
        uint2 u = make_uint2(*reinterpret_cast<uint32_t*>(&h0),
                             *reinterpret_cast<uint32_t*>(&h1));
        *reinterpret_cast<uint2*>(&sW[k * SW + nc * 4]) = u;
    }
    __syncthreads();

    int lane = tid & 31;
    int wid = tid >> 5;
    int mg = wid >> 1;
    int wh = wid & 1;
    int lrow = lane & 15;
    int lcol = lane >> 4;

    float acc[8][4] = {};
    uint32_t aBase = (uint32_t)__cvta_generic_to_shared(sA) +
                     ((mg * 16 + lrow) * SA + lcol * 8) * 2;
    uint32_t wBase = (uint32_t)__cvta_generic_to_shared(sW) +
                     (lrow * SW + wh * 64 + lcol * 8) * 2;

#pragma unroll
    for (int ks = 0; ks < IN / 16; ++ks) {
        uint32_t a0, a1, a2, a3;
        ldsm_x4(a0, a1, a2, a3, aBase + ks * 32);
#pragma unroll
        for (int j = 0; j < 4; ++j) {
            uint32_t b0, b1, b2, b3;
            ldsm_x4_t(b0, b1, b2, b3, wBase + ks * 16 * SW * 2 + j * 32);
            mma16816(acc[2 * j], a0, a1, a2, a3, b0, b1);
            mma16816(acc[2 * j + 1], a0, a1, a2, a3, b2, b3);
        }
    }

    int r_lo = row0 + mg * 16 + (lane >> 2);
    int cbase = wh * 64 + (lane & 3) * 2;
#pragma unroll
    for (int j = 0; j < 8; ++j) {
        int col = cbase + j * 8;
        if (r_lo < N_NODES) {
            __half2 h = __floats2half2_rn(acc[j][0], acc[j][1]);
            *reinterpret_cast<__half2*>(&g_mh[(size_t)r_lo * HIDDEN + col]) = h;
        }
        if (r_lo + 8 < N_NODES) {
            __half2 h = __floats2half2_rn(acc[j][2], acc[j][3]);
            *reinterpret_cast<__half2*>(&g_mh[(size_t)(r_lo + 8) * HIDDEN + col]) = h;
        }
    }
}

// ---------------- edge aggregate (CSR): 16 lanes per dst node ----------------
// g_xh[n] = relu( sum coef*g_mh[src] + g_mh[n]*dinv^2 + b )  stored fp16.
// 2 nodes per warp (2 independent chains) + depth-2 prefetch -> MLP ~4.
__global__ void __launch_bounds__(256) k_edge(const float* __restrict__ b) {
    int t = blockIdx.x * 256 + threadIdx.x;
    int node = t >> 4;
    int lane = threadIdx.x & 15;          // 8 cols per lane
    if (node >= N_NODES) return;
    int r0 = g_rowptr[node];
    int r1 = g_rowptr[node + 1];
    const uint4* mh4 = reinterpret_cast<const uint4*>(g_mh);   // 8 halves per uint4

    unsigned long long acc0 = 0, acc1 = 0, acc2 = 0, acc3 = 0;
    int j = r0;
    int2 e;
    uint4 raw;
    if (j < r1) {
        e = g_csr[j];
        raw = mh4[(size_t)e.x * (HIDDEN / 8) + lane];
    }
    while (j < r1) {
        int jn = j + 1;
        int2 e2;
        uint4 raw2;
        if (jn < r1) {                      // prefetch next edge
            e2 = g_csr[jn];
            raw2 = mh4[(size_t)e2.x * (HIDDEN / 8) + lane];
        }
        float c = __int_as_float(e.y);
        unsigned long long cc = pack2(c, c);
        float2 f0 = __half22float2(*reinterpret_cast<__half2*>(&raw.x));
        float2 f1 = __half22float2(*reinterpret_cast<__half2*>(&raw.y));
        float2 f2 = __half22float2(*reinterpret_cast<__half2*>(&raw.z));
        float2 f3 = __half22float2(*reinterpret_cast<__half2*>(&raw.w));
        fma2(acc0, cc, pack2(f0.x, f0.y));
        fma2(acc1, cc, pack2(f1.x, f1.y));
        fma2(acc2, cc, pack2(f2.x, f2.y));
        fma2(acc3, cc, pack2(f3.x, f3.y));
        e = e2;
        raw = raw2;
        j = jn;
    }
    // self-loop + bias + relu
    uint4 ms = mh4[(size_t)node * (HIDDEN / 8) + lane];
    float dv = g_dinv[node];
    float sc = dv * dv;
    float4 bb0 = *reinterpret_cast<const float4*>(&b[lane * 8]);
    float4 bb1 = *reinterpret_cast<const float4*>(&b[lane * 8 + 4]);
    float2 m0 = __half22float2(*reinterpret_cast<__half2*>(&ms.x));
    float2 m1 = __half22float2(*reinterpret_cast<__half2*>(&ms.y));
    float2 m2 = __half22float2(*reinterpret_cast<__half2*>(&ms.z));
    float2 m3 = __half22float2(*reinterpret_cast<__half2*>(&ms.w));
    float2 a0 = unpack2(acc0), a1 = unpack2(acc1);
    float2 a2 = unpack2(acc2), a3 = unpack2(acc3);
    float o0 = fmaxf(a0.x + fmaf(m0.x, sc, bb0.x), 0.f);
    float o1 = fmaxf(a0.y + fmaf(m0.y, sc, bb0.y), 0.f);
    float o2 = fmaxf(a1.x + fmaf(m1.x, sc, bb0.z), 0.f);
    float o3 = fmaxf(a1.y + fmaf(m1.y, sc, bb0.w), 0.f);
    float o4 = fmaxf(a2.x + fmaf(m2.x, sc, bb1.x), 0.f);
    float o5 = fmaxf(a2.y + fmaf(m2.y, sc, bb1.y), 0.f);
    float o6 = fmaxf(a3.x + fmaf(m3.x, sc, bb1.z), 0.f);
    float o7 = fmaxf(a3.y + fmaf(m3.y, sc, bb1.w), 0.f);
    __half2 h0 = __floats2half2_rn(o0, o1);
    __half2 h1 = __floats2half2_rn(o2, o3);
    __half2 h2 = __floats2half2_rn(o4, o5);
    __half2 h3 = __floats2half2_rn(o6, o7);
    uint4 u = make_uint4(*reinterpret_cast<uint32_t*>(&h0),
                         *reinterpret_cast<uint32_t*>(&h1),
                         *reinterpret_cast<uint32_t*>(&h2),
                         *reinterpret_cast<uint32_t*>(&h3));
    reinterpret_cast<uint4*>(g_xh)[(size_t)node * (HIDDEN / 8) + lane] = u;
}

// ---------------- pooling (batch sorted -> register accumulation) ----------------
#define POOL_CHUNK 512
__global__ void __launch_bounds__(128) k_pool(const void* batch) {
    int is64 = g_is64;
    int t = threadIdx.x;
    int n0 = blockIdx.x * POOL_CHUNK;
    int n1 = n0 + POOL_CHUNK;
    if (n1 > N_NODES) n1 = N_NODES;
    float acc = 0.0f, cnt = 0.0f;
    int cur = -1;
    for (int n = n0; n < n1; ++n) {
        int gidx = (int)load_idx(batch, n, is64);
        if (gidx != cur) {
            if (cur >= 0) {
                atomicAdd(&g_pool[cur * HIDDEN + t], acc);
                if (t == 0) atomicAdd(&g_cnt[cur], cnt);
            }
            cur = gidx;
            acc = 0.0f;
            cnt = 0.0f;
        }
        acc += __half2float(g_xh[(size_t)n * HIDDEN + t]);   // already relu'd
        cnt += 1.0f;
    }
    if (cur >= 0) {
        atomicAdd(&g_pool[cur * HIDDEN + t], acc);
        if (t == 0) atomicAdd(&g_cnt[cur], cnt);
    }
}

// ---------------- final: out = (pool / cnt) @ Wp + bp ----------------
__global__ void k_final(const float* __restrict__ Wp, const float* __restrict__ bp,
                        float* __restrict__ out) {
    int t = blockIdx.x * blockDim.x + threadIdx.x;
    if (t >= N_GRAPHS * HIDDEN) return;
    int g = t >> 7;
    int j = t & 127;
    float inv = 1.0f / fmaxf(g_cnt[g], 1.0f);
    float acc = bp[j];
#pragma unroll 8
    for (int k = 0; k < HIDDEN; ++k)
        acc = fmaf(g_pool[g * HIDDEN + k] * inv, Wp[k * HIDDEN + j], acc);
    out[t] = acc;
}

// ---------------- launch ----------------
extern "C" void kernel_launch(void* const* d_in, const int* in_sizes, int n_in,
                              void* d_out, int out_size) {
    const void* x     = d_in[0];
    const void* ei    = d_in[1];
    const void* batch = d_in[2];
    const float* emb  = (const float*)d_in[3];
    const float* W1   = (const float*)d_in[4];
    const float* b1   = (const float*)d_in[5];
    const float* W2   = (const float*)d_in[6];
    const float* b2   = (const float*)d_in[7];
    const float* W3   = (const float*)d_in[8];
    const float* b3   = (const float*)d_in[9];
    const float* Wp   = (const float*)d_in[10];
    const float* bp   = (const float*)d_in[11];
    float* out = (float*)d_out;

    constexpr int SMEM1 = (64 * (EMBED + 8) + EMBED * (HIDDEN + 8)) * 2;    // 26.6 KB
    constexpr int SMEM2 = (64 * (HIDDEN + 8) + HIDDEN * (HIDDEN + 8)) * 2;  // 52.2 KB
    cudaFuncSetAttribute(k_gemm<EMBED, true>,
                         cudaFuncAttributeMaxDynamicSharedMemorySize, SMEM1);
    cudaFuncSetAttribute(k_gemm<HIDDEN, false>,
                         cudaFuncAttributeMaxDynamicSharedMemorySize, SMEM2);

    const int GEMM_GRID = (N_NODES + 63) / 64;            // 1563
    const int EDGE_GRID = (N_NODES * 16 + 255) / 256;     // 6250

    k_init<<<(N_NODES + 255) / 256, 256>>>(ei);                              // 0
    k_count_embed<<<(N_EDGES + 255) / 256, 256>>>(ei, x, emb);               // 1
    k_scan1<<<(N_NODES + 255) / 256, 256>>>();                               // 2
    k_gemm<EMBED, true><<<GEMM_GRID, 256, SMEM1>>>(W1);                      // 3 <- ncu
    k_scan2<<<1, 512>>>();                                                   // 4
    k_scan3<<<(N_NODES + 255) / 256, 256>>>();                               // 5
    k_csr<<<(N_EDGES + 255) / 256, 256>>>(ei);                               // 6
    k_edge<<<EDGE_GRID, 256>>>(b1);                                          // 7
    k_gemm<HIDDEN, false><<<GEMM_GRID, 256, SMEM2>>>(W2);                    // 8
    k_edge<<<EDGE_GRID, 256>>>(b2);                                          // 9
    k_gemm<HIDDEN, false><<<GEMM_GRID, 256, SMEM2>>>(W3);                    // 10
    k_edge<<<EDGE_GRID, 256>>>(b3);                                          // 11
    k_pool<<<(N_NODES + POOL_CHUNK - 1) / POOL_CHUNK, 128>>>(batch);         // 12
    k_final<<<(N_GRAPHS * HIDDEN + 255) / 256, 256>>>(Wp, bp, out);          // 13
}

// round 12
// speedup vs baseline: 2.9851x; 1.1679x over previous
#include <cuda_runtime.h>
#include <cuda_fp16.h>
#include <cstdint>

#define N_NODES 100000
#define N_EDGES 1600000
#define N_GRAPHS 64
#define EMBED 64
#define HIDDEN 128

// ---------------- scratch (static device globals; no allocation) ----------------
// Referenced ONLY from device code (host-side use of __device__ symbols binds
// the shadow symbol -> the R9 guard violation).
__device__ __half g_h0h[N_NODES * EMBED];       // embedded features fp16 12.8 MB
__device__ __half g_mh[N_NODES * HIDDEN];       // dinv * (h @ W), fp16   25.6 MB
__device__ __half g_xh[N_NODES * HIDDEN];       // relu'd activations     25.6 MB
__device__ int    g_csr32[N_EDGES];             // src only (coef folded)  6.4 MB
__device__ int    g_rowptr[N_NODES + 1];
__device__ int    g_cursor[N_NODES];
__device__ int    g_deg[N_NODES];
__device__ float  g_dinv[N_NODES];
__device__ int    g_part[512];
__device__ float  g_pool[N_GRAPHS * HIDDEN];
__device__ float  g_cnt[N_GRAPHS];
__device__ int    g_is64;

// ---------------- f32x2 helpers (edge accumulate) ----------------
__device__ __forceinline__ unsigned long long pack2(float x, float y) {
    unsigned long long r;
    asm("mov.b64 %0, {%1, %2};" : "=l"(r) : "f"(x), "f"(y));
    return r;
}
__device__ __forceinline__ float2 unpack2(unsigned long long v) {
    float2 r;
    asm("mov.b64 {%0, %1}, %2;" : "=f"(r.x), "=f"(r.y) : "l"(v));
    return r;
}
__device__ __forceinline__ void fma2(unsigned long long& d, unsigned long long a,
                                     unsigned long long b) {
    asm("fma.rn.f32x2 %0, %1, %2, %0;" : "+l"(d) : "l"(a), "l"(b));
}

// ---------------- mma / ldmatrix helpers ----------------
__device__ __forceinline__ void ldsm_x4(uint32_t& r0, uint32_t& r1, uint32_t& r2,
                                        uint32_t& r3, uint32_t addr) {
    asm volatile("ldmatrix.sync.aligned.m8n8.x4.shared.b16 {%0,%1,%2,%3}, [%4];"
                 : "=r"(r0), "=r"(r1), "=r"(r2), "=r"(r3) : "r"(addr));
}
__device__ __forceinline__ void ldsm_x4_t(uint32_t& r0, uint32_t& r1, uint32_t& r2,
                                          uint32_t& r3, uint32_t addr) {
    asm volatile("ldmatrix.sync.aligned.m8n8.x4.trans.shared.b16 {%0,%1,%2,%3}, [%4];"
                 : "=r"(r0), "=r"(r1), "=r"(r2), "=r"(r3) : "r"(addr));
}
__device__ __forceinline__ void mma16816(float* c, uint32_t a0, uint32_t a1,
                                         uint32_t a2, uint32_t a3,
                                         uint32_t b0, uint32_t b1) {
    asm volatile(
        "mma.sync.aligned.m16n8k16.row.col.f32.f16.f16.f32 "
        "{%0,%1,%2,%3}, {%4,%5,%6,%7}, {%8,%9}, {%0,%1,%2,%3};"
        : "+f"(c[0]), "+f"(c[1]), "+f"(c[2]), "+f"(c[3])
        : "r"(a0), "r"(a1), "r"(a2), "r"(a3), "r"(b0), "r"(b1));
}

__device__ __forceinline__ long long load_idx(const void* p, int i, int is64) {
    if (is64) return ((const long long*)p)[i];
    return (long long)((const int*)p)[i];
}

// ---------------- init: zero counters + parallel dtype detection ----------------
__global__ void k_init(const void* ei) {
    int i = blockIdx.x * blockDim.x + threadIdx.x;
    if (i < N_NODES) g_deg[i] = 0;
    if (i < N_GRAPHS * HIDDEN) g_pool[i] = 0.0f;
    if (i < N_GRAPHS) g_cnt[i] = 0.0f;
    if (blockIdx.x == 0) {
        __shared__ int s_ok;
        if (threadIdx.x == 0) s_ok = 1;
        __syncthreads();
        const unsigned long long* p = (const unsigned long long*)ei;
        int bad = 0;
        for (int t = threadIdx.x; t < 1000; t += 256)
            if (p[t] >= (unsigned long long)N_NODES) bad = 1;
        if (bad) atomicAnd(&s_ok, 0);
        __syncthreads();
        if (threadIdx.x == 0) g_is64 = s_ok;
    }
}

// ---------------- fused: degree count + embedding gather ----------------
__global__ void k_count_embed(const void* ei, const void* x,
                              const float* __restrict__ emb) {
    int is64 = g_is64;
    int t = blockIdx.x * blockDim.x + threadIdx.x;
    if (t < N_EDGES) {
        int d = (int)load_idx(ei, N_EDGES + t, is64);
        atomicAdd(&g_deg[d], 1);
    }
    if (t < N_NODES * (EMBED / 4)) {
        int node = t >> 4;
        int q = t & 15;
        long long xi = load_idx(x, node, is64);
        float4 v = reinterpret_cast<const float4*>(emb)[xi * (EMBED / 4) + q];
        __half2 h0 = __floats2half2_rn(v.x, v.y);
        __half2 h1 = __floats2half2_rn(v.z, v.w);
        uint2 u = make_uint2(*reinterpret_cast<uint32_t*>(&h0),
                             *reinterpret_cast<uint32_t*>(&h1));
        reinterpret_cast<uint2*>(g_h0h)[t] = u;
    }
}

// ---------------- prep scans + CSR build ----------------
__global__ void __launch_bounds__(256) k_scan1() {
    __shared__ int s[256];
    int tid = threadIdx.x;
    int n = blockIdx.x * 256 + tid;
    int d = (n < N_NODES) ? g_deg[n] : 0;
    if (n < N_NODES) g_dinv[n] = rsqrtf((float)d + 1.0f);
    s[tid] = d;
    __syncthreads();
#pragma unroll
    for (int off = 1; off < 256; off <<= 1) {
        int v = (tid >= off) ? s[tid - off] : 0;
        __syncthreads();
        s[tid] += v;
        __syncthreads();
    }
    if (n < N_NODES) g_rowptr[n] = s[tid] - d;
    if (tid == 255) g_part[blockIdx.x] = s[255];
}

__global__ void __launch_bounds__(512) k_scan2() {
    __shared__ int s[512];
    int tid = threadIdx.x;
    int v0 = (tid < 391) ? g_part[tid] : 0;
    s[tid] = v0;
    __syncthreads();
#pragma unroll
    for (int off = 1; off < 512; off <<= 1) {
        int v = (tid >= off) ? s[tid - off] : 0;
        __syncthreads();
        s[tid] += v;
        __syncthreads();
    }
    if (tid < 391) g_part[tid] = s[tid] - v0;
}

__global__ void k_scan3() {
    int n = blockIdx.x * blockDim.x + threadIdx.x;
    if (n < N_NODES) {
        int v = g_rowptr[n] + g_part[n >> 8];
        g_rowptr[n] = v;
        g_cursor[n] = v;
    }
    if (n == 0) g_rowptr[N_NODES] = N_EDGES;
}

// CSR stores ONLY src: coef = dinv[s]*dinv[d] is factored as a pre-scale of
// messages (dinv[s], applied in the GEMM epilogue) and a post-scale of the
// per-node sum (dinv[d], applied in the edge epilogue).
__global__ void k_csr(const void* ei) {
    int is64 = g_is64;
    int e = blockIdx.x * blockDim.x + threadIdx.x;
    if (e < N_EDGES) {
        int s = (int)load_idx(ei, e, is64);
        int d = (int)load_idx(ei, N_EDGES + e, is64);
        int pos = atomicAdd(&g_cursor[d], 1);
        g_csr32[pos] = s;
    }
}

// ---------------- tensor-core GEMM: g_mh = half(dinv[row] * (in @ W)) --------
// 512 threads = 16 warps as 8(m) x 2(n); block tile 128 rows x 128 cols.
// W staged+converted once per 128 rows (half the staging work vs 64-row tiles).
template <int IN, bool FROM_H0>
__global__ void __launch_bounds__(512) k_gemm(const float* __restrict__ W) {
    const __half* in = FROM_H0 ? g_h0h : g_xh;
    constexpr int SA = IN + 8;
    constexpr int SW = HIDDEN + 8;
    extern __shared__ __half smem[];
    __half* sA = smem;                 // 128 x SA
    __half* sW = smem + 128 * SA;      // IN x SW
    int tid = threadIdx.x;
    int row0 = blockIdx.x * 128;

    // stage A (fp16 straight copy; already relu'd where applicable)
    for (int t = tid; t < 128 * IN / 4; t += 512) {
        int r = t / (IN / 4);
        int kc = t % (IN / 4);
        int row = row0 + r;
        uint2 v = make_uint2(0u, 0u);
        if (row < N_NODES)
            v = *reinterpret_cast<const uint2*>(&in[(size_t)row * IN + kc * 4]);
        *reinterpret_cast<uint2*>(&sA[r * SA + kc * 4]) = v;
    }
    // stage W (fp32 -> fp16)
    for (int t = tid; t < IN * HIDDEN / 4; t += 512) {
        int k = t / (HIDDEN / 4);
        int nc = t % (HIDDEN / 4);
        float4 v = *reinterpret_cast<const float4*>(&W[k * HIDDEN + nc * 4]);
        __half2 h0 = __floats2half2_rn(v.x, v.y);
        __half2 h1 = __floats2half2_rn(v.z, v.w);
        uint2 u = make_uint2(*reinterpret_cast<uint32_t*>(&h0),
                             *reinterpret_cast<uint32_t*>(&h1));
        *reinterpret_cast<uint2*>(&sW[k * SW + nc * 4]) = u;
    }
    __syncthreads();

    int lane = tid & 31;
    int wid = tid >> 5;
    int mg = wid >> 1;                 // 0..7 : rows mg*16..+15
    int wh = wid & 1;                  // 0..1 : cols wh*64..+63
    int lrow = lane & 15;
    int lcol = lane >> 4;

    float acc[8][4] = {};
    uint32_t aBase = (uint32_t)__cvta_generic_to_shared(sA) +
                     ((mg * 16 + lrow) * SA + lcol * 8) * 2;
    uint32_t wBase = (uint32_t)__cvta_generic_to_shared(sW) +
                     (lrow * SW + wh * 64 + lcol * 8) * 2;

#pragma unroll
    for (int ks = 0; ks < IN / 16; ++ks) {
        uint32_t a0, a1, a2, a3;
        ldsm_x4(a0, a1, a2, a3, aBase + ks * 32);
#pragma unroll
        for (int j = 0; j < 4; ++j) {
            uint32_t b0, b1, b2, b3;
            ldsm_x4_t(b0, b1, b2, b3, wBase + ks * 16 * SW * 2 + j * 32);
            mma16816(acc[2 * j], a0, a1, a2, a3, b0, b1);
            mma16816(acc[2 * j + 1], a0, a1, a2, a3, b2, b3);
        }
    }

    // epilogue: scale by dinv[row], store fp16
    int r_lo = row0 + mg * 16 + (lane >> 2);
    int cbase = wh * 64 + (lane & 3) * 2;
    float dv_lo = (r_lo < N_NODES) ? g_dinv[r_lo] : 0.f;
    float dv_hi = (r_lo + 8 < N_NODES) ? g_dinv[r_lo + 8] : 0.f;
#pragma unroll
    for (int j = 0; j < 8; ++j) {
        int col = cbase + j * 8;
        if (r_lo < N_NODES) {
            __half2 h = __floats2half2_rn(acc[j][0] * dv_lo, acc[j][1] * dv_lo);
            *reinterpret_cast<__half2*>(&g_mh[(size_t)r_lo * HIDDEN + col]) = h;
        }
        if (r_lo + 8 < N_NODES) {
            __half2 h = __floats2half2_rn(acc[j][2] * dv_hi, acc[j][3] * dv_hi);
            *reinterpret_cast<__half2*>(&g_mh[(size_t)(r_lo + 8) * HIDDEN + col]) = h;
        }
    }
}

// ---------------- edge aggregate (CSR): 16 lanes per dst node ----------------
// g_xh[n] = relu( dinv[n] * ( sum_src m'[src] + m'[n] ) + b ),  m' = dinv*m.
// 2 nodes per warp (2 independent chains) + depth-2 prefetch.
__global__ void __launch_bounds__(256) k_edge(const float* __restrict__ b) {
    int t = blockIdx.x * 256 + threadIdx.x;
    int node = t >> 4;
    int lane = threadIdx.x & 15;          // 8 cols per lane
    if (node >= N_NODES) return;
    int r0 = g_rowptr[node];
    int r1 = g_rowptr[node + 1];
    const uint4* mh4 = reinterpret_cast<const uint4*>(g_mh);   // 8 halves per uint4
    const unsigned long long ONE = pack2(1.0f, 1.0f);

    unsigned long long acc0 = 0, acc1 = 0, acc2 = 0, acc3 = 0;
    int j = r0;
    uint4 raw;
    if (j < r1) {
        int s = g_csr32[j];
        raw = mh4[(size_t)s * (HIDDEN / 8) + lane];
    }
    while (j < r1) {
        int jn = j + 1;
        uint4 raw2;
        if (jn < r1) {                      // prefetch next edge
            int s2 = g_csr32[jn];
            raw2 = mh4[(size_t)s2 * (HIDDEN / 8) + lane];
        }
        float2 f0 = __half22float2(*reinterpret_cast<__half2*>(&raw.x));
        float2 f1 = __half22float2(*reinterpret_cast<__half2*>(&raw.y));
        float2 f2 = __half22float2(*reinterpret_cast<__half2*>(&raw.z));
        float2 f3 = __half22float2(*reinterpret_cast<__half2*>(&raw.w));
        fma2(acc0, ONE, pack2(f0.x, f0.y));
        fma2(acc1, ONE, pack2(f1.x, f1.y));
        fma2(acc2, ONE, pack2(f2.x, f2.y));
        fma2(acc3, ONE, pack2(f3.x, f3.y));
        raw = raw2;
        j = jn;
    }
    // self term, post-scale by dinv[n], bias, relu
    uint4 ms = mh4[(size_t)node * (HIDDEN / 8) + lane];
    float dv = g_dinv[node];
    float4 bb0 = *reinterpret_cast<const float4*>(&b[lane * 8]);
    float4 bb1 = *reinterpret_cast<const float4*>(&b[lane * 8 + 4]);
    float2 m0 = __half22float2(*reinterpret_cast<__half2*>(&ms.x));
    float2 m1 = __half22float2(*reinterpret_cast<__half2*>(&ms.y));
    float2 m2 = __half22float2(*reinterpret_cast<__half2*>(&ms.z));
    float2 m3 = __half22float2(*reinterpret_cast<__half2*>(&ms.w));
    float2 a0 = unpack2(acc0), a1 = unpack2(acc1);
    float2 a2 = unpack2(acc2), a3 = unpack2(acc3);
    float o0 = fmaxf(fmaf(a0.x + m0.x, dv, bb0.x), 0.f);
    float o1 = fmaxf(fmaf(a0.y + m0.y, dv, bb0.y), 0.f);
    float o2 = fmaxf(fmaf(a1.x + m1.x, dv, bb0.z), 0.f);
    float o3 = fmaxf(fmaf(a1.y + m1.y, dv, bb0.w), 0.f);
    float o4 = fmaxf(fmaf(a2.x + m2.x, dv, bb1.x), 0.f);
    float o5 = fmaxf(fmaf(a2.y + m2.y, dv, bb1.y), 0.f);
    float o6 = fmaxf(fmaf(a3.x + m3.x, dv, bb1.z), 0.f);
    float o7 = fmaxf(fmaf(a3.y + m3.y, dv, bb1.w), 0.f);
    __half2 h0 = __floats2half2_rn(o0, o1);
    __half2 h1 = __floats2half2_rn(o2, o3);
    __half2 h2 = __floats2half2_rn(o4, o5);
    __half2 h3 = __floats2half2_rn(o6, o7);
    uint4 u = make_uint4(*reinterpret_cast<uint32_t*>(&h0),
                         *reinterpret_cast<uint32_t*>(&h1),
                         *reinterpret_cast<uint32_t*>(&h2),
                         *reinterpret_cast<uint32_t*>(&h3));
    reinterpret_cast<uint4*>(g_xh)[(size_t)node * (HIDDEN / 8) + lane] = u;
}

// ---------------- pooling (batch sorted -> register accumulation) ----------------
#define POOL_CHUNK 512
__global__ void __launch_bounds__(128) k_pool(const void* batch) {
    int is64 = g_is64;
    int t = threadIdx.x;
    int n0 = blockIdx.x * POOL_CHUNK;
    int n1 = n0 + POOL_CHUNK;
    if (n1 > N_NODES) n1 = N_NODES;
    float acc = 0.0f, cnt = 0.0f;
    int cur = -1;
    for (int n = n0; n < n1; ++n) {
        int gidx = (int)load_idx(batch, n, is64);
        if (gidx != cur) {
            if (cur >= 0) {
                atomicAdd(&g_pool[cur * HIDDEN + t], acc);
                if (t == 0) atomicAdd(&g_cnt[cur], cnt);
            }
            cur = gidx;
            acc = 0.0f;
            cnt = 0.0f;
        }
        acc += __half2float(g_xh[(size_t)n * HIDDEN + t]);   // already relu'd
        cnt += 1.0f;
    }
    if (cur >= 0) {
        atomicAdd(&g_pool[cur * HIDDEN + t], acc);
        if (t == 0) atomicAdd(&g_cnt[cur], cnt);
    }
}

// ---------------- final: out = (pool / cnt) @ Wp + bp ----------------
__global__ void k_final(const float* __restrict__ Wp, const float* __restrict__ bp,
                        float* __restrict__ out) {
    int t = blockIdx.x * blockDim.x + threadIdx.x;
    if (t >= N_GRAPHS * HIDDEN) return;
    int g = t >> 7;
    int j = t & 127;
    float inv = 1.0f / fmaxf(g_cnt[g], 1.0f);
    float acc = bp[j];
#pragma unroll 8
    for (int k = 0; k < HIDDEN; ++k)
        acc = fmaf(g_pool[g * HIDDEN + k] * inv, Wp[k * HIDDEN + j], acc);
    out[t] = acc;
}

// ---------------- launch ----------------
extern "C" void kernel_launch(void* const* d_in, const int* in_sizes, int n_in,
                              void* d_out, int out_size) {
    const void* x     = d_in[0];
    const void* ei    = d_in[1];
    const void* batch = d_in[2];
    const float* emb  = (const float*)d_in[3];
    const float* W1   = (const float*)d_in[4];
    const float* b1   = (const float*)d_in[5];
    const float* W2   = (const float*)d_in[6];
    const float* b2   = (const float*)d_in[7];
    const float* W3   = (const float*)d_in[8];
    const float* b3   = (const float*)d_in[9];
    const float* Wp   = (const float*)d_in[10];
    const float* bp   = (const float*)d_in[11];
    float* out = (float*)d_out;

    constexpr int SMEM1 = (128 * (EMBED + 8) + EMBED * (HIDDEN + 8)) * 2;    // 35.8 KB
    constexpr int SMEM2 = (128 * (HIDDEN + 8) + HIDDEN * (HIDDEN + 8)) * 2;  // 69.6 KB
    cudaFuncSetAttribute(k_gemm<EMBED, true>,
                         cudaFuncAttributeMaxDynamicSharedMemorySize, SMEM1);
    cudaFuncSetAttribute(k_gemm<HIDDEN, false>,
                         cudaFuncAttributeMaxDynamicSharedMemorySize, SMEM2);

    const int GEMM_GRID = (N_NODES + 127) / 128;          // 782
    const int EDGE_GRID = (N_NODES * 16 + 255) / 256;     // 6250

    k_init<<<(N_NODES + 255) / 256, 256>>>(ei);                              // 0
    k_count_embed<<<(N_EDGES + 255) / 256, 256>>>(ei, x, emb);               // 1
    k_scan1<<<(N_NODES + 255) / 256, 256>>>();                               // 2
    k_gemm<EMBED, true><<<GEMM_GRID, 512, SMEM1>>>(W1);                      // 3 <- ncu
    k_scan2<<<1, 512>>>();                                                   // 4
    k_scan3<<<(N_NODES + 255) / 256, 256>>>();                               // 5
    k_csr<<<(N_EDGES + 255) / 256, 256>>>(ei);                               // 6
    k_edge<<<EDGE_GRID, 256>>>(b1);                                          // 7
    k_gemm<HIDDEN, false><<<GEMM_GRID, 512, SMEM2>>>(W2);                    // 8
    k_edge<<<EDGE_GRID, 256>>>(b2);                                          // 9
    k_gemm<HIDDEN, false><<<GEMM_GRID, 512, SMEM2>>>(W3);                    // 10
    k_edge<<<EDGE_GRID, 256>>>(b3);                                          // 11
    k_pool<<<(N_NODES + POOL_CHUNK - 1) / POOL_CHUNK, 128>>>(batch);         // 12
    k_final<<<(N_GRAPHS * HIDDEN + 255) / 256, 256>>>(Wp, bp, out);          // 13
}

// round 13
// speedup vs baseline: 3.0296x; 1.0149x over previous
#include <cuda_runtime.h>
#include <cuda_fp16.h>
#include <cstdint>

#define N_NODES 100000
#define N_EDGES 1600000
#define N_GRAPHS 64
#define EMBED 64
#define HIDDEN 128

// ---------------- scratch (static device globals; no allocation) ----------------
// Referenced ONLY from device code (host-side use of __device__ symbols binds
// the shadow symbol -> the R9 guard violation).
__device__ __half g_h0h[N_NODES * EMBED];       // embedded features fp16 12.8 MB
__device__ __half g_mh[N_NODES * HIDDEN];       // dinv * (h @ W), fp16   25.6 MB
__device__ __half g_xh[N_NODES * HIDDEN];       // relu'd activations     25.6 MB
__device__ int    g_csr32[N_EDGES];             // src only (coef folded)  6.4 MB
__device__ int    g_rowptr[N_NODES + 1];
__device__ int    g_cursor[N_NODES];
__device__ int    g_deg[N_NODES];
__device__ float  g_dinv[N_NODES];
__device__ int    g_part[512];
__device__ float  g_pool[N_GRAPHS * HIDDEN];
__device__ float  g_cnt[N_GRAPHS];
__device__ int    g_is64;

// ---------------- f32x2 helpers (edge accumulate) ----------------
__device__ __forceinline__ unsigned long long pack2(float x, float y) {
    unsigned long long r;
    asm("mov.b64 %0, {%1, %2};" : "=l"(r) : "f"(x), "f"(y));
    return r;
}
__device__ __forceinline__ float2 unpack2(unsigned long long v) {
    float2 r;
    asm("mov.b64 {%0, %1}, %2;" : "=f"(r.x), "=f"(r.y) : "l"(v));
    return r;
}
__device__ __forceinline__ void fma2(unsigned long long& d, unsigned long long a,
                                     unsigned long long b) {
    asm("fma.rn.f32x2 %0, %1, %2, %0;" : "+l"(d) : "l"(a), "l"(b));
}

// ---------------- mma / ldmatrix helpers ----------------
__device__ __forceinline__ void ldsm_x4(uint32_t& r0, uint32_t& r1, uint32_t& r2,
                                        uint32_t& r3, uint32_t addr) {
    asm volatile("ldmatrix.sync.aligned.m8n8.x4.shared.b16 {%0,%1,%2,%3}, [%4];"
                 : "=r"(r0), "=r"(r1), "=r"(r2), "=r"(r3) : "r"(addr));
}
__device__ __forceinline__ void ldsm_x4_t(uint32_t& r0, uint32_t& r1, uint32_t& r2,
                                          uint32_t& r3, uint32_t addr) {
    asm volatile("ldmatrix.sync.aligned.m8n8.x4.trans.shared.b16 {%0,%1,%2,%3}, [%4];"
                 : "=r"(r0), "=r"(r1), "=r"(r2), "=r"(r3) : "r"(addr));
}
__device__ __forceinline__ void mma16816(float* c, uint32_t a0, uint32_t a1,
                                         uint32_t a2, uint32_t a3,
                                         uint32_t b0, uint32_t b1) {
    asm volatile(
        "mma.sync.aligned.m16n8k16.row.col.f32.f16.f16.f32 "
        "{%0,%1,%2,%3}, {%4,%5,%6,%7}, {%8,%9}, {%0,%1,%2,%3};"
        : "+f"(c[0]), "+f"(c[1]), "+f"(c[2]), "+f"(c[3])
        : "r"(a0), "r"(a1), "r"(a2), "r"(a3), "r"(b0), "r"(b1));
}

__device__ __forceinline__ long long load_idx(const void* p, int i, int is64) {
    if (is64) return ((const long long*)p)[i];
    return (long long)((const int*)p)[i];
}

// ---------------- init: zero counters + parallel dtype detection ----------------
__global__ void k_init(const void* ei) {
    int i = blockIdx.x * blockDim.x + threadIdx.x;
    if (i < N_NODES) g_deg[i] = 0;
    if (i < N_GRAPHS * HIDDEN) g_pool[i] = 0.0f;
    if (i < N_GRAPHS) g_cnt[i] = 0.0f;
    if (blockIdx.x == 0) {
        __shared__ int s_ok;
        if (threadIdx.x == 0) s_ok = 1;
        __syncthreads();
        const unsigned long long* p = (const unsigned long long*)ei;
        int bad = 0;
        for (int t = threadIdx.x; t < 1000; t += 256)
            if (p[t] >= (unsigned long long)N_NODES) bad = 1;
        if (bad) atomicAnd(&s_ok, 0);
        __syncthreads();
        if (threadIdx.x == 0) g_is64 = s_ok;
    }
}

// ---------------- fused: degree count + embedding gather ----------------
__global__ void k_count_embed(const void* ei, const void* x,
                              const float* __restrict__ emb) {
    int is64 = g_is64;
    int t = blockIdx.x * blockDim.x + threadIdx.x;
    if (t < N_EDGES) {
        int d = (int)load_idx(ei, N_EDGES + t, is64);
        atomicAdd(&g_deg[d], 1);
    }
    if (t < N_NODES * (EMBED / 4)) {
        int node = t >> 4;
        int q = t & 15;
        long long xi = load_idx(x, node, is64);
        float4 v = reinterpret_cast<const float4*>(emb)[xi * (EMBED / 4) + q];
        __half2 h0 = __floats2half2_rn(v.x, v.y);
        __half2 h1 = __floats2half2_rn(v.z, v.w);
        uint2 u = make_uint2(*reinterpret_cast<uint32_t*>(&h0),
                             *reinterpret_cast<uint32_t*>(&h1));
        reinterpret_cast<uint2*>(g_h0h)[t] = u;
    }
}

// ---------------- prep scans + CSR build ----------------
__global__ void __launch_bounds__(256) k_scan1() {
    __shared__ int s[256];
    int tid = threadIdx.x;
    int n = blockIdx.x * 256 + tid;
    int d = (n < N_NODES) ? g_deg[n] : 0;
    if (n < N_NODES) g_dinv[n] = rsqrtf((float)d + 1.0f);
    s[tid] = d;
    __syncthreads();
#pragma unroll
    for (int off = 1; off < 256; off <<= 1) {
        int v = (tid >= off) ? s[tid - off] : 0;
        __syncthreads();
        s[tid] += v;
        __syncthreads();
    }
    if (n < N_NODES) g_rowptr[n] = s[tid] - d;
    if (tid == 255) g_part[blockIdx.x] = s[255];
}

__global__ void __launch_bounds__(512) k_scan2() {
    __shared__ int s[512];
    int tid = threadIdx.x;
    int v0 = (tid < 391) ? g_part[tid] : 0;
    s[tid] = v0;
    __syncthreads();
#pragma unroll
    for (int off = 1; off < 512; off <<= 1) {
        int v = (tid >= off) ? s[tid - off] : 0;
        __syncthreads();
        s[tid] += v;
        __syncthreads();
    }
    if (tid < 391) g_part[tid] = s[tid] - v0;
}

__global__ void k_scan3() {
    int n = blockIdx.x * blockDim.x + threadIdx.x;
    if (n < N_NODES) {
        int v = g_rowptr[n] + g_part[n >> 8];
        g_rowptr[n] = v;
        g_cursor[n] = v;
    }
    if (n == 0) g_rowptr[N_NODES] = N_EDGES;
}

// CSR stores ONLY src: coef = dinv[s]*dinv[d] is factored as a pre-scale of
// messages (dinv[s], applied in the GEMM epilogue) and a post-scale of the
// per-node sum (dinv[d], applied in the edge epilogue).
__global__ void k_csr(const void* ei) {
    int is64 = g_is64;
    int e = blockIdx.x * blockDim.x + threadIdx.x;
    if (e < N_EDGES) {
        int s = (int)load_idx(ei, e, is64);
        int d = (int)load_idx(ei, N_EDGES + e, is64);
        int pos = atomicAdd(&g_cursor[d], 1);
        g_csr32[pos] = s;
    }
}

// ---------------- tensor-core GEMM: g_mh = half(dinv[row] * (in @ W)) --------
// 512 threads = 16 warps as 8(m) x 2(n); block covers 256 rows as 2 chunks of
// 128 through a single 128-row A buffer. W staged+converted ONCE per block.
// Grid 391 <= 148 SMs x 3 blocks (smem-bound) => single wave.
template <int IN, bool FROM_H0>
__global__ void __launch_bounds__(512) k_gemm(const float* __restrict__ W) {
    const __half* in = FROM_H0 ? g_h0h : g_xh;
    constexpr int SA = IN + 8;
    constexpr int SW = HIDDEN + 8;
    extern __shared__ __half smem[];
    __half* sA = smem;                 // 128 x SA (chunk buffer, reused)
    __half* sW = smem + 128 * SA;      // IN x SW
    int tid = threadIdx.x;

    // stage W once (fp32 -> fp16)
    for (int t = tid; t < IN * HIDDEN / 4; t += 512) {
        int k = t / (HIDDEN / 4);
        int nc = t % (HIDDEN / 4);
        float4 v = *reinterpret_cast<const float4*>(&W[k * HIDDEN + nc * 4]);
        __half2 h0 = __floats2half2_rn(v.x, v.y);
        __half2 h1 = __floats2half2_rn(v.z, v.w);
        uint2 u = make_uint2(*reinterpret_cast<uint32_t*>(&h0),
                             *reinterpret_cast<uint32_t*>(&h1));
        *reinterpret_cast<uint2*>(&sW[k * SW + nc * 4]) = u;
    }

    int lane = tid & 31;
    int wid = tid >> 5;
    int mg = wid >> 1;                 // 0..7 : rows mg*16..+15 within chunk
    int wh = wid & 1;                  // 0..1 : cols wh*64..+63
    int lrow = lane & 15;
    int lcol = lane >> 4;
    uint32_t aBase = (uint32_t)__cvta_generic_to_shared(sA) +
                     ((mg * 16 + lrow) * SA + lcol * 8) * 2;
    uint32_t wBase = (uint32_t)__cvta_generic_to_shared(sW) +
                     (lrow * SW + wh * 64 + lcol * 8) * 2;

#pragma unroll
    for (int c = 0; c < 2; ++c) {
        int crow0 = blockIdx.x * 256 + c * 128;
        // Barrier: (c==0) orders W staging before mma; (c==1) protects sA
        // reuse against chunk-0 readers.
        __syncthreads();
        // stage A chunk (fp16 straight copy; already relu'd where applicable)
        for (int t = tid; t < 128 * IN / 4; t += 512) {
            int r = t / (IN / 4);
            int kc = t % (IN / 4);
            int row = crow0 + r;
            uint2 v = make_uint2(0u, 0u);
            if (row < N_NODES)
                v = *reinterpret_cast<const uint2*>(&in[(size_t)row * IN + kc * 4]);
            *reinterpret_cast<uint2*>(&sA[r * SA + kc * 4]) = v;
        }
        __syncthreads();

        float acc[8][4] = {};
#pragma unroll
        for (int ks = 0; ks < IN / 16; ++ks) {
            uint32_t a0, a1, a2, a3;
            ldsm_x4(a0, a1, a2, a3, aBase + ks * 32);
#pragma unroll
            for (int j = 0; j < 4; ++j) {
                uint32_t b0, b1, b2, b3;
                ldsm_x4_t(b0, b1, b2, b3, wBase + ks * 16 * SW * 2 + j * 32);
                mma16816(acc[2 * j], a0, a1, a2, a3, b0, b1);
                mma16816(acc[2 * j + 1], a0, a1, a2, a3, b2, b3);
            }
        }

        // epilogue: scale by dinv[row], store fp16
        int r_lo = crow0 + mg * 16 + (lane >> 2);
        int cbase = wh * 64 + (lane & 3) * 2;
        float dv_lo = (r_lo < N_NODES) ? g_dinv[r_lo] : 0.f;
        float dv_hi = (r_lo + 8 < N_NODES) ? g_dinv[r_lo + 8] : 0.f;
#pragma unroll
        for (int j = 0; j < 8; ++j) {
            int col = cbase + j * 8;
            if (r_lo < N_NODES) {
                __half2 h = __floats2half2_rn(acc[j][0] * dv_lo, acc[j][1] * dv_lo);
                *reinterpret_cast<__half2*>(&g_mh[(size_t)r_lo * HIDDEN + col]) = h;
            }
            if (r_lo + 8 < N_NODES) {
                __half2 h = __floats2half2_rn(acc[j][2] * dv_hi, acc[j][3] * dv_hi);
                *reinterpret_cast<__half2*>(&g_mh[(size_t)(r_lo + 8) * HIDDEN + col]) = h;
            }
        }
    }
}

// ---------------- edge aggregate (CSR): 16 lanes per dst node ----------------
// g_xh[n] = relu( dinv[n] * ( sum_src m'[src] + m'[n] ) + b ),  m' = dinv*m.
// 2 nodes per warp (2 independent chains) + depth-2 prefetch.
__global__ void __launch_bounds__(256) k_edge(const float* __restrict__ b) {
    int t = blockIdx.x * 256 + threadIdx.x;
    int node = t >> 4;
    int lane = threadIdx.x & 15;          // 8 cols per lane
    if (node >= N_NODES) return;
    int r0 = g_rowptr[node];
    int r1 = g_rowptr[node + 1];
    const uint4* mh4 = reinterpret_cast<const uint4*>(g_mh);   // 8 halves per uint4
    const unsigned long long ONE = pack2(1.0f, 1.0f);

    unsigned long long acc0 = 0, acc1 = 0, acc2 = 0, acc3 = 0;
    int j = r0;
    uint4 raw;
    if (j < r1) {
        int s = g_csr32[j];
        raw = mh4[(size_t)s * (HIDDEN / 8) + lane];
    }
    while (j < r1) {
        int jn = j + 1;
        uint4 raw2;
        if (jn < r1) {                      // prefetch next edge
            int s2 = g_csr32[jn];
            raw2 = mh4[(size_t)s2 * (HIDDEN / 8) + lane];
        }
        float2 f0 = __half22float2(*reinterpret_cast<__half2*>(&raw.x));
        float2 f1 = __half22float2(*reinterpret_cast<__half2*>(&raw.y));
        float2 f2 = __half22float2(*reinterpret_cast<__half2*>(&raw.z));
        float2 f3 = __half22float2(*reinterpret_cast<__half2*>(&raw.w));
        fma2(acc0, ONE, pack2(f0.x, f0.y));
        fma2(acc1, ONE, pack2(f1.x, f1.y));
        fma2(acc2, ONE, pack2(f2.x, f2.y));
        fma2(acc3, ONE, pack2(f3.x, f3.y));
        raw = raw2;
        j = jn;
    }
    // self term, post-scale by dinv[n], bias, relu
    uint4 ms = mh4[(size_t)node * (HIDDEN / 8) + lane];
    float dv = g_dinv[node];
    float4 bb0 = *reinterpret_cast<const float4*>(&b[lane * 8]);
    float4 bb1 = *reinterpret_cast<const float4*>(&b[lane * 8 + 4]);
    float2 m0 = __half22float2(*reinterpret_cast<__half2*>(&ms.x));
    float2 m1 = __half22float2(*reinterpret_cast<__half2*>(&ms.y));
    float2 m2 = __half22float2(*reinterpret_cast<__half2*>(&ms.z));
    float2 m3 = __half22float2(*reinterpret_cast<__half2*>(&ms.w));
    float2 a0 = unpack2(acc0), a1 = unpack2(acc1);
    float2 a2 = unpack2(acc2), a3 = unpack2(acc3);
    float o0 = fmaxf(fmaf(a0.x + m0.x, dv, bb0.x), 0.f);
    float o1 = fmaxf(fmaf(a0.y + m0.y, dv, bb0.y), 0.f);
    float o2 = fmaxf(fmaf(a1.x + m1.x, dv, bb0.z), 0.f);
    float o3 = fmaxf(fmaf(a1.y + m1.y, dv, bb0.w), 0.f);
    float o4 = fmaxf(fmaf(a2.x + m2.x, dv, bb1.x), 0.f);
    float o5 = fmaxf(fmaf(a2.y + m2.y, dv, bb1.y), 0.f);
    float o6 = fmaxf(fmaf(a3.x + m3.x, dv, bb1.z), 0.f);
    float o7 = fmaxf(fmaf(a3.y + m3.y, dv, bb1.w), 0.f);
    __half2 h0 = __floats2half2_rn(o0, o1);
    __half2 h1 = __floats2half2_rn(o2, o3);
    __half2 h2 = __floats2half2_rn(o4, o5);
    __half2 h3 = __floats2half2_rn(o6, o7);
    uint4 u = make_uint4(*reinterpret_cast<uint32_t*>(&h0),
                         *reinterpret_cast<uint32_t*>(&h1),
                         *reinterpret_cast<uint32_t*>(&h2),
                         *reinterpret_cast<uint32_t*>(&h3));
    reinterpret_cast<uint4*>(g_xh)[(size_t)node * (HIDDEN / 8) + lane] = u;
}

// ---------------- pooling (batch sorted -> register accumulation) ----------------
#define POOL_CHUNK 512
__global__ void __launch_bounds__(128) k_pool(const void* batch) {
    int is64 = g_is64;
    int t = threadIdx.x;
    int n0 = blockIdx.x * POOL_CHUNK;
    int n1 = n0 + POOL_CHUNK;
    if (n1 > N_NODES) n1 = N_NODES;
    float acc = 0.0f, cnt = 0.0f;
    int cur = -1;
    for (int n = n0; n < n1; ++n) {
        int gidx = (int)load_idx(batch, n, is64);
        if (gidx != cur) {
            if (cur >= 0) {
                atomicAdd(&g_pool[cur * HIDDEN + t], acc);
                if (t == 0) atomicAdd(&g_cnt[cur], cnt);
            }
            cur = gidx;
            acc = 0.0f;
            cnt = 0.0f;
        }
        acc += __half2float(g_xh[(size_t)n * HIDDEN + t]);   // already relu'd
        cnt += 1.0f;
    }
    if (cur >= 0) {
        atomicAdd(&g_pool[cur * HIDDEN + t], acc);
        if (t == 0) atomicAdd(&g_cnt[cur], cnt);
    }
}

// ---------------- final: out = (pool / cnt) @ Wp + bp ----------------
__global__ void k_final(const float* __restrict__ Wp, const float* __restrict__ bp,
                        float* __restrict__ out) {
    int t = blockIdx.x * blockDim.x + threadIdx.x;
    if (t >= N_GRAPHS * HIDDEN) return;
    int g = t >> 7;
    int j = t & 127;
    float inv = 1.0f / fmaxf(g_cnt[g], 1.0f);
    float acc = bp[j];
#pragma unroll 8
    for (int k = 0; k < HIDDEN; ++k)
        acc = fmaf(g_pool[g * HIDDEN + k] * inv, Wp[k * HIDDEN + j], acc);
    out[t] = acc;
}

// ---------------- launch ----------------
extern "C" void kernel_launch(void* const* d_in, const int* in_sizes, int n_in,
                              void* d_out, int out_size) {
    const void* x     = d_in[0];
    const void* ei    = d_in[1];
    const void* batch = d_in[2];
    const float* emb  = (const float*)d_in[3];
    const float* W1   = (const float*)d_in[4];
    const float* b1   = (const float*)d_in[5];
    const float* W2   = (const float*)d_in[6];
    const float* b2   = (const float*)d_in[7];
    const float* W3   = (const float*)d_in[8];
    const float* b3   = (const float*)d_in[9];
    const float* Wp   = (const float*)d_in[10];
    const float* bp   = (const float*)d_in[11];
    float* out = (float*)d_out;

    constexpr int SMEM1 = (128 * (EMBED + 8) + EMBED * (HIDDEN + 8)) * 2;    // 35.8 KB
    constexpr int SMEM2 = (128 * (HIDDEN + 8) + HIDDEN * (HIDDEN + 8)) * 2;  // 69.6 KB
    cudaFuncSetAttribute(k_gemm<EMBED, true>,
                         cudaFuncAttributeMaxDynamicSharedMemorySize, SMEM1);
    cudaFuncSetAttribute(k_gemm<HIDDEN, false>,
                         cudaFuncAttributeMaxDynamicSharedMemorySize, SMEM2);

    const int GEMM_GRID = (N_NODES + 255) / 256;          // 391 -> single wave
    const int EDGE_GRID = (N_NODES * 16 + 255) / 256;     // 6250

    k_init<<<(N_NODES + 255) / 256, 256>>>(ei);                              // 0
    k_count_embed<<<(N_EDGES + 255) / 256, 256>>>(ei, x, emb);               // 1
    k_scan1<<<(N_NODES + 255) / 256, 256>>>();                               // 2
    k_gemm<EMBED, true><<<GEMM_GRID, 512, SMEM1>>>(W1);                      // 3 <- ncu
    k_scan2<<<1, 512>>>();                                                   // 4
    k_scan3<<<(N_NODES + 255) / 256, 256>>>();                               // 5
    k_csr<<<(N_EDGES + 255) / 256, 256>>>(ei);                               // 6
    k_edge<<<EDGE_GRID, 256>>>(b1);                                          // 7
    k_gemm<HIDDEN, false><<<GEMM_GRID, 512, SMEM2>>>(W2);                    // 8
    k_edge<<<EDGE_GRID, 256>>>(b2);                                          // 9
    k_gemm<HIDDEN, false><<<GEMM_GRID, 512, SMEM2>>>(W3);                    // 10
    k_edge<<<EDGE_GRID, 256>>>(b3);                                          // 11
    k_pool<<<(N_NODES + POOL_CHUNK - 1) / POOL_CHUNK, 128>>>(batch);         // 12
    k_final<<<(N_GRAPHS * HIDDEN + 255) / 256, 256>>>(Wp, bp, out);          // 13
}

// round 16
// speedup vs baseline: 3.1054x; 1.0250x over previous
#include <cuda_runtime.h>
#include <cuda_fp16.h>
#include <cstdint>

#define N_NODES 100000
#define N_EDGES 1600000
#define N_GRAPHS 64
#define EMBED 64
#define HIDDEN 128
#define GEMM_GRID 296   // 2 blocks/SM on 148 SMs -> single wave

// ---------------- scratch (static device globals; no allocation) ----------------
// Referenced ONLY from device code (host-side use of __device__ symbols binds
// the shadow symbol -> the R9 guard violation).
__device__ __half g_h0h[N_NODES * EMBED];       // embedded features fp16 12.8 MB
__device__ __half g_mh[N_NODES * HIDDEN];       // dinv * (h @ W), fp16   25.6 MB
__device__ __half g_xh[N_NODES * HIDDEN];       // relu'd activations     25.6 MB
__device__ int    g_csr32[N_EDGES];             // src only (coef folded)  6.4 MB
__device__ int    g_rowptr[N_NODES + 1];
__device__ int    g_cursor[N_NODES];
__device__ int    g_deg[N_NODES];
__device__ float  g_dinv[N_NODES];
__device__ int    g_part[512];
__device__ float  g_pool[N_GRAPHS * HIDDEN];
__device__ float  g_cnt[N_GRAPHS];
__device__ int    g_is64;

// ---------------- f32x2 helpers (edge accumulate) ----------------
__device__ __forceinline__ unsigned long long pack2(float x, float y) {
    unsigned long long r;
    asm("mov.b64 %0, {%1, %2};" : "=l"(r) : "f"(x), "f"(y));
    return r;
}
__device__ __forceinline__ float2 unpack2(unsigned long long v) {
    float2 r;
    asm("mov.b64 {%0, %1}, %2;" : "=f"(r.x), "=f"(r.y) : "l"(v));
    return r;
}
__device__ __forceinline__ void fma2(unsigned long long& d, unsigned long long a,
                                     unsigned long long b) {
    asm("fma.rn.f32x2 %0, %1, %2, %0;" : "+l"(d) : "l"(a), "l"(b));
}

// ---------------- cp.async helpers ----------------
__device__ __forceinline__ void cp16(uint32_t dst, const void* src, int srcsize) {
    asm volatile("cp.async.cg.shared.global [%0], [%1], 16, %2;"
                 :: "r"(dst), "l"(src), "r"(srcsize) : "memory");
}
#define CP_COMMIT() asm volatile("cp.async.commit_group;" ::: "memory")
#define CP_WAIT(n)  asm volatile("cp.async.wait_group %0;" :: "n"(n) : "memory")

// ---------------- mma / ldmatrix helpers ----------------
__device__ __forceinline__ void ldsm_x4(uint32_t& r0, uint32_t& r1, uint32_t& r2,
                                        uint32_t& r3, uint32_t addr) {
    asm volatile("ldmatrix.sync.aligned.m8n8.x4.shared.b16 {%0,%1,%2,%3}, [%4];"
                 : "=r"(r0), "=r"(r1), "=r"(r2), "=r"(r3) : "r"(addr));
}
__device__ __forceinline__ void ldsm_x4_t(uint32_t& r0, uint32_t& r1, uint32_t& r2,
                                          uint32_t& r3, uint32_t addr) {
    asm volatile("ldmatrix.sync.aligned.m8n8.x4.trans.shared.b16 {%0,%1,%2,%3}, [%4];"
                 : "=r"(r0), "=r"(r1), "=r"(r2), "=r"(r3) : "r"(addr));
}
__device__ __forceinline__ void mma16816(float* c, uint32_t a0, uint32_t a1,
                                         uint32_t a2, uint32_t a3,
                                         uint32_t b0, uint32_t b1) {
    asm volatile(
        "mma.sync.aligned.m16n8k16.row.col.f32.f16.f16.f32 "
        "{%0,%1,%2,%3}, {%4,%5,%6,%7}, {%8,%9}, {%0,%1,%2,%3};"
        : "+f"(c[0]), "+f"(c[1]), "+f"(c[2]), "+f"(c[3])
        : "r"(a0), "r"(a1), "r"(a2), "r"(a3), "r"(b0), "r"(b1));
}

__device__ __forceinline__ long long load_idx(const void* p, int i, int is64) {
    if (is64) return ((const long long*)p)[i];
    return (long long)((const int*)p)[i];
}

// ---------------- init: zero counters + parallel dtype detection ----------------
__global__ void k_init(const void* ei) {
    int i = blockIdx.x * blockDim.x + threadIdx.x;
    if (i < N_NODES) g_deg[i] = 0;
    if (i < N_GRAPHS * HIDDEN) g_pool[i] = 0.0f;
    if (i < N_GRAPHS) g_cnt[i] = 0.0f;
    if (blockIdx.x == 0) {
        __shared__ int s_ok;
        if (threadIdx.x == 0) s_ok = 1;
        __syncthreads();
        const unsigned long long* p = (const unsigned long long*)ei;
        int bad = 0;
        for (int t = threadIdx.x; t < 1000; t += 256)
            if (p[t] >= (unsigned long long)N_NODES) bad = 1;
        if (bad) atomicAnd(&s_ok, 0);
        __syncthreads();
        if (threadIdx.x == 0) g_is64 = s_ok;
    }
}

// ---------------- fused: degree count + embedding gather ----------------
__global__ void k_count_embed(const void* ei, const void* x,
                              const float* __restrict__ emb) {
    int is64 = g_is64;
    int t = blockIdx.x * blockDim.x + threadIdx.x;
    if (t < N_EDGES) {
        int d = (int)load_idx(ei, N_EDGES + t, is64);
        atomicAdd(&g_deg[d], 1);
    }
    if (t < N_NODES * (EMBED / 4)) {
        int node = t >> 4;
        int q = t & 15;
        long long xi = load_idx(x, node, is64);
        float4 v = reinterpret_cast<const float4*>(emb)[xi * (EMBED / 4) + q];
        __half2 h0 = __floats2half2_rn(v.x, v.y);
        __half2 h1 = __floats2half2_rn(v.z, v.w);
        uint2 u = make_uint2(*reinterpret_cast<uint32_t*>(&h0),
                             *reinterpret_cast<uint32_t*>(&h1));
        reinterpret_cast<uint2*>(g_h0h)[t] = u;
    }
}

// ---------------- prep scans + CSR build ----------------
__global__ void __launch_bounds__(256) k_scan1() {
    __shared__ int s[256];
    int tid = threadIdx.x;
    int n = blockIdx.x * 256 + tid;
    int d = (n < N_NODES) ? g_deg[n] : 0;
    if (n < N_NODES) g_dinv[n] = rsqrtf((float)d + 1.0f);
    s[tid] = d;
    __syncthreads();
#pragma unroll
    for (int off = 1; off < 256; off <<= 1) {
        int v = (tid >= off) ? s[tid - off] : 0;
        __syncthreads();
        s[tid] += v;
        __syncthreads();
    }
    if (n < N_NODES) g_rowptr[n] = s[tid] - d;
    if (tid == 255) g_part[blockIdx.x] = s[255];
}

__global__ void __launch_bounds__(512) k_scan2() {
    __shared__ int s[512];
    int tid = threadIdx.x;
    int v0 = (tid < 391) ? g_part[tid] : 0;
    s[tid] = v0;
    __syncthreads();
#pragma unroll
    for (int off = 1; off < 512; off <<= 1) {
        int v = (tid >= off) ? s[tid - off] : 0;
        __syncthreads();
        s[tid] += v;
        __syncthreads();
    }
    if (tid < 391) g_part[tid] = s[tid] - v0;
}

__global__ void k_scan3() {
    int n = blockIdx.x * blockDim.x + threadIdx.x;
    if (n < N_NODES) {
        int v = g_rowptr[n] + g_part[n >> 8];
        g_rowptr[n] = v;
        g_cursor[n] = v;
    }
    if (n == 0) g_rowptr[N_NODES] = N_EDGES;
}

// CSR stores ONLY src: coef = dinv[s]*dinv[d] is factored as a pre-scale of
// messages (dinv[s], GEMM epilogue) and a post-scale of the sum (dinv[d],
// edge epilogue).
__global__ void k_csr(const void* ei) {
    int is64 = g_is64;
    int e = blockIdx.x * blockDim.x + threadIdx.x;
    if (e < N_EDGES) {
        int s = (int)load_idx(ei, e, is64);
        int d = (int)load_idx(ei, N_EDGES + e, is64);
        int pos = atomicAdd(&g_cursor[d], 1);
        g_csr32[pos] = s;
    }
}

// ---------------- tensor-core GEMM: g_mh = half(dinv[row] * (in @ W)) --------
// Persistent blocks over strided 128-row chunks with cp.async DOUBLE-BUFFERED
// A staging: chunk j+1 loads overlap chunk j MMA (hides ~577cyc DRAM latency
// that stalled the serial-staged version). W staged once per block.
// 512 threads = 16 warps as 8(m) x 2(n); grid 296 = 2 blocks/SM, single wave.
template <int IN, bool FROM_H0>
__global__ void __launch_bounds__(512) k_gemm(const float* __restrict__ W) {
    const __half* in = FROM_H0 ? g_h0h : g_xh;
    constexpr int SA = IN + 8;
    constexpr int SW = HIDDEN + 8;
    constexpr int NCHUNK = (N_NODES + 127) / 128;   // 782
    constexpr int PER_ROW = IN / 8;                 // 16B lines per A row
    constexpr int LINES = 128 * PER_ROW;            // 16B lines per chunk
    extern __shared__ __half smem[];
    __half* sW = smem;                              // IN x SW
    __half* sA0 = smem + IN * SW;                   // 128 x SA
    __half* sA1 = sA0 + 128 * SA;                   // 128 x SA
    int tid = threadIdx.x;

    // stage W once (fp32 -> fp16)
    for (int t = tid; t < IN * HIDDEN / 4; t += 512) {
        int k = t / (HIDDEN / 4);
        int nc = t % (HIDDEN / 4);
        float4 v = *reinterpret_cast<const float4*>(&W[k * HIDDEN + nc * 4]);
        __half2 h0 = __floats2half2_rn(v.x, v.y);
        __half2 h1 = __floats2half2_rn(v.z, v.w);
        uint2 u = make_uint2(*reinterpret_cast<uint32_t*>(&h0),
                             *reinterpret_cast<uint32_t*>(&h1));
        *reinterpret_cast<uint2*>(&sW[k * SW + nc * 4]) = u;
    }

    uint32_t sA0u = (uint32_t)__cvta_generic_to_shared(sA0);
    uint32_t sA1u = (uint32_t)__cvta_generic_to_shared(sA1);

    int lane = tid & 31;
    int wid = tid >> 5;
    int mg = wid >> 1;                 // 0..7 : rows mg*16..+15 within chunk
    int wh = wid & 1;                  // 0..1 : cols wh*64..+63
    int lrow = lane & 15;
    int lcol = lane >> 4;
    uint32_t aOff = ((mg * 16 + lrow) * SA + lcol * 8) * 2;
    uint32_t wBase = (uint32_t)__cvta_generic_to_shared(sW) +
                     (lrow * SW + wh * 64 + lcol * 8) * 2;

    // initial prefetch: chunk blockIdx.x -> buffer 0
    {
        int chunk = blockIdx.x;
        for (int t = tid; t < LINES; t += 512) {
            int r = t / PER_ROW;
            int col = t - r * PER_ROW;
            int row = chunk * 128 + r;
            int ok = row < N_NODES;
            const __half* src = in + (size_t)(ok ? row : 0) * IN + col * 8;
            cp16(sA0u + (r * SA + col * 8) * 2, src, ok ? 16 : 0);
        }
        CP_COMMIT();
    }

    int j = 0;
    for (int c = blockIdx.x; c < NCHUNK; c += GEMM_GRID, ++j) {
        int cn = c + GEMM_GRID;
        if (cn < NCHUNK) {
            // prefetch next chunk into the other buffer
            uint32_t sAu = (j & 1) ? sA0u : sA1u;
            for (int t = tid; t < LINES; t += 512) {
                int r = t / PER_ROW;
                int col = t - r * PER_ROW;
                int row = cn * 128 + r;
                int ok = row < N_NODES;
                const __half* src = in + (size_t)(ok ? row : 0) * IN + col * 8;
                cp16(sAu + (r * SA + col * 8) * 2, src, ok ? 16 : 0);
            }
            CP_COMMIT();
            CP_WAIT(1);
        } else {
            CP_WAIT(0);
        }
        __syncthreads();   // A buf ready (also orders W staging on j==0)

        uint32_t aBase = ((j & 1) ? sA1u : sA0u) + aOff;
        float acc[8][4] = {};
#pragma unroll
        for (int ks = 0; ks < IN / 16; ++ks) {
            uint32_t a0, a1, a2, a3;
            ldsm_x4(a0, a1, a2, a3, aBase + ks * 32);
#pragma unroll
            for (int jj = 0; jj < 4; ++jj) {
                uint32_t b0, b1, b2, b3;
                ldsm_x4_t(b0, b1, b2, b3, wBase + ks * 16 * SW * 2 + jj * 32);
                mma16816(acc[2 * jj], a0, a1, a2, a3, b0, b1);
                mma16816(acc[2 * jj + 1], a0, a1, a2, a3, b2, b3);
            }
        }

        // epilogue: scale by dinv[row], store fp16
        int r_lo = c * 128 + mg * 16 + (lane >> 2);
        int cbase = wh * 64 + (lane & 3) * 2;
        float dv_lo = (r_lo < N_NODES) ? g_dinv[r_lo] : 0.f;
        float dv_hi = (r_lo + 8 < N_NODES) ? g_dinv[r_lo + 8] : 0.f;
#pragma unroll
        for (int jj = 0; jj < 8; ++jj) {
            int col = cbase + jj * 8;
            if (r_lo < N_NODES) {
                __half2 h = __floats2half2_rn(acc[jj][0] * dv_lo, acc[jj][1] * dv_lo);
                *reinterpret_cast<__half2*>(&g_mh[(size_t)r_lo * HIDDEN + col]) = h;
            }
            if (r_lo + 8 < N_NODES) {
                __half2 h = __floats2half2_rn(acc[jj][2] * dv_hi, acc[jj][3] * dv_hi);
                *reinterpret_cast<__half2*>(&g_mh[(size_t)(r_lo + 8) * HIDDEN + col]) = h;
            }
        }
        __syncthreads();   // all reads of this buf done before it's re-prefetched
    }
}

// ---------------- edge aggregate (CSR): 16 lanes per dst node ----------------
// g_xh[n] = relu( dinv[n] * ( sum_src m'[src] + m'[n] ) + b ),  m' = dinv*m.
// 2 nodes per warp (2 independent chains) + depth-2 prefetch.
__global__ void __launch_bounds__(256) k_edge(const float* __restrict__ b) {
    int t = blockIdx.x * 256 + threadIdx.x;
    int node = t >> 4;
    int lane = threadIdx.x & 15;          // 8 cols per lane
    if (node >= N_NODES) return;
    int r0 = g_rowptr[node];
    int r1 = g_rowptr[node + 1];
    const uint4* mh4 = reinterpret_cast<const uint4*>(g_mh);   // 8 halves per uint4
    const unsigned long long ONE = pack2(1.0f, 1.0f);

    unsigned long long acc0 = 0, acc1 = 0, acc2 = 0, acc3 = 0;
    int j = r0;
    uint4 raw;
    if (j < r1) {
        int s = g_csr32[j];
        raw = mh4[(size_t)s * (HIDDEN / 8) + lane];
    }
    while (j < r1) {
        int jn = j + 1;
        uint4 raw2;
        if (jn < r1) {                      // prefetch next edge
            int s2 = g_csr32[jn];
            raw2 = mh4[(size_t)s2 * (HIDDEN / 8) + lane];
        }
        float2 f0 = __half22float2(*reinterpret_cast<__half2*>(&raw.x));
        float2 f1 = __half22float2(*reinterpret_cast<__half2*>(&raw.y));
        float2 f2 = __half22float2(*reinterpret_cast<__half2*>(&raw.z));
        float2 f3 = __half22float2(*reinterpret_cast<__half2*>(&raw.w));
        fma2(acc0, ONE, pack2(f0.x, f0.y));
        fma2(acc1, ONE, pack2(f1.x, f1.y));
        fma2(acc2, ONE, pack2(f2.x, f2.y));
        fma2(acc3, ONE, pack2(f3.x, f3.y));
        raw = raw2;
        j = jn;
    }
    // self term, post-scale by dinv[n], bias, relu
    uint4 ms = mh4[(size_t)node * (HIDDEN / 8) + lane];
    float dv = g_dinv[node];
    float4 bb0 = *reinterpret_cast<const float4*>(&b[lane * 8]);
    float4 bb1 = *reinterpret_cast<const float4*>(&b[lane * 8 + 4]);
    float2 m0 = __half22float2(*reinterpret_cast<__half2*>(&ms.x));
    float2 m1 = __half22float2(*reinterpret_cast<__half2*>(&ms.y));
    float2 m2 = __half22float2(*reinterpret_cast<__half2*>(&ms.z));
    float2 m3 = __half22float2(*reinterpret_cast<__half2*>(&ms.w));
    float2 a0 = unpack2(acc0), a1 = unpack2(acc1);
    float2 a2 = unpack2(acc2), a3 = unpack2(acc3);
    float o0 = fmaxf(fmaf(a0.x + m0.x, dv, bb0.x), 0.f);
    float o1 = fmaxf(fmaf(a0.y + m0.y, dv, bb0.y), 0.f);
    float o2 = fmaxf(fmaf(a1.x + m1.x, dv, bb0.z), 0.f);
    float o3 = fmaxf(fmaf(a1.y + m1.y, dv, bb0.w), 0.f);
    float o4 = fmaxf(fmaf(a2.x + m2.x, dv, bb1.x), 0.f);
    float o5 = fmaxf(fmaf(a2.y + m2.y, dv, bb1.y), 0.f);
    float o6 = fmaxf(fmaf(a3.x + m3.x, dv, bb1.z), 0.f);
    float o7 = fmaxf(fmaf(a3.y + m3.y, dv, bb1.w), 0.f);
    __half2 h0 = __floats2half2_rn(o0, o1);
    __half2 h1 = __floats2half2_rn(o2, o3);
    __half2 h2 = __floats2half2_rn(o4, o5);
    __half2 h3 = __floats2half2_rn(o6, o7);
    uint4 u = make_uint4(*reinterpret_cast<uint32_t*>(&h0),
                         *reinterpret_cast<uint32_t*>(&h1),
                         *reinterpret_cast<uint32_t*>(&h2),
                         *reinterpret_cast<uint32_t*>(&h3));
    reinterpret_cast<uint4*>(g_xh)[(size_t)node * (HIDDEN / 8) + lane] = u;
}

// ---------------- pooling (batch sorted -> register accumulation) ----------------
#define POOL_CHUNK 512
__global__ void __launch_bounds__(128) k_pool(const void* batch) {
    int is64 = g_is64;
    int t = threadIdx.x;
    int n0 = blockIdx.x * POOL_CHUNK;
    int n1 = n0 + POOL_CHUNK;
    if (n1 > N_NODES) n1 = N_NODES;
    float acc = 0.0f, cnt = 0.0f;
    int cur = -1;
    for (int n = n0; n < n1; ++n) {
        int gidx = (int)load_idx(batch, n, is64);
        if (gidx != cur) {
            if (cur >= 0) {
                atomicAdd(&g_pool[cur * HIDDEN + t], acc);
                if (t == 0) atomicAdd(&g_cnt[cur], cnt);
            }
            cur = gidx;
            acc = 0.0f;
            cnt = 0.0f;
        }
        acc += __half2float(g_xh[(size_t)n * HIDDEN + t]);   // already relu'd
        cnt += 1.0f;
    }
    if (cur >= 0) {
        atomicAdd(&g_pool[cur * HIDDEN + t], acc);
        if (t == 0) atomicAdd(&g_cnt[cur], cnt);
    }
}

// ---------------- final: out = (pool / cnt) @ Wp + bp ----------------
__global__ void k_final(const float* __restrict__ Wp, const float* __restrict__ bp,
                        float* __restrict__ out) {
    int t = blockIdx.x * blockDim.x + threadIdx.x;
    if (t >= N_GRAPHS * HIDDEN) return;
    int g = t >> 7;
    int j = t & 127;
    float inv = 1.0f / fmaxf(g_cnt[g], 1.0f);
    float acc = bp[j];
#pragma unroll 8
    for (int k = 0; k < HIDDEN; ++k)
        acc = fmaf(g_pool[g * HIDDEN + k] * inv, Wp[k * HIDDEN + j], acc);
    out[t] = acc;
}

// ---------------- launch ----------------
extern "C" void kernel_launch(void* const* d_in, const int* in_sizes, int n_in,
                              void* d_out, int out_size) {
    const void* x     = d_in[0];
    const void* ei    = d_in[1];
    const void* batch = d_in[2];
    const float* emb  = (const float*)d_in[3];
    const float* W1   = (const float*)d_in[4];
    const float* b1   = (const float*)d_in[5];
    const float* W2   = (const float*)d_in[6];
    const float* b2   = (const float*)d_in[7];
    const float* W3   = (const float*)d_in[8];
    const float* b3   = (const float*)d_in[9];
    const float* Wp   = (const float*)d_in[10];
    const float* bp   = (const float*)d_in[11];
    float* out = (float*)d_out;

    // smem: W + 2x A chunk buffers
    constexpr int SMEM1 = (EMBED * (HIDDEN + 8) + 2 * 128 * (EMBED + 8)) * 2;   // 53 KB
    constexpr int SMEM2 = (HIDDEN * (HIDDEN + 8) + 2 * 128 * (HIDDEN + 8)) * 2; // 102 KB
    cudaFuncSetAttribute(k_gemm<EMBED, true>,
                         cudaFuncAttributeMaxDynamicSharedMemorySize, SMEM1);
    cudaFuncSetAttribute(k_gemm<HIDDEN, false>,
                         cudaFuncAttributeMaxDynamicSharedMemorySize, SMEM2);

    const int EDGE_GRID = (N_NODES * 16 + 255) / 256;     // 6250

    k_init<<<(N_NODES + 255) / 256, 256>>>(ei);                              // 0
    k_count_embed<<<(N_EDGES + 255) / 256, 256>>>(ei, x, emb);               // 1
    k_scan1<<<(N_NODES + 255) / 256, 256>>>();                               // 2
    k_gemm<EMBED, true><<<GEMM_GRID, 512, SMEM1>>>(W1);                      // 3 <- ncu
    k_scan2<<<1, 512>>>();                                                   // 4
    k_scan3<<<(N_NODES + 255) / 256, 256>>>();                               // 5
    k_csr<<<(N_EDGES + 255) / 256, 256>>>(ei);                               // 6
    k_edge<<<EDGE_GRID, 256>>>(b1);                                          // 7
    k_gemm<HIDDEN, false><<<GEMM_GRID, 512, SMEM2>>>(W2);                    // 8
    k_edge<<<EDGE_GRID, 256>>>(b2);                                          // 9
    k_gemm<HIDDEN, false><<<GEMM_GRID, 512, SMEM2>>>(W3);                    // 10
    k_edge<<<EDGE_GRID, 256>>>(b3);                                          // 11
    k_pool<<<(N_NODES + POOL_CHUNK - 1) / POOL_CHUNK, 128>>>(batch);         // 12
    k_final<<<(N_GRAPHS * HIDDEN + 255) / 256, 256>>>(Wp, bp, out);          // 13
}